// round 7
// baseline (speedup 1.0000x reference)
#include <cuda_runtime.h>
#include <cuda_bf16.h>
#include <math.h>
#include <stdint.h>
typedef __nv_bfloat16 bf16;

#define DD    2560
#define HDIM  320
#define NH    8
#define SEGL  1024
#define STOT  4096
#define BATCH 2
#define MMEM  128
#define NSEG  4
#define MBIG  (BATCH*SEGL)
#define MSM   (BATCH*MMEM)
#define BKT   32
#define BN    160
#define WN    80
#define NT    10

// fp32 scratch
__device__ float g_qr[MBIG*DD], g_gate[MBIG*DD], g_kw[MBIG*DD], g_vw[MBIG*DD];
__device__ float g_kr[MSM*DD], g_vr[MSM*DD], g_qw[MSM*DD], g_nm[MSM*DD];
__device__ float g_memA[MSM*DD], g_memB[MSM*DD];
// bf16 scratch
#define WMAT (DD*DD)
__device__ __align__(16) bf16 g_whi[11LL*WMAT], g_wlo[11LL*WMAT];
__device__ __align__(16) bf16 g_hidhi[BATCH*STOT*DD], g_hidlo[BATCH*STOT*DD];
__device__ __align__(16) bf16 g_chi[MBIG*DD], g_clo[MBIG*DD];
__device__ __align__(16) bf16 g_ahi[MBIG*DD], g_alo[MBIG*DD];
__device__ __align__(16) bf16 g_awhi[MSM*DD], g_awlo[MSM*DD];
__device__ __align__(16) bf16 g_cathi[MSM*2*DD], g_catlo[MSM*2*DD];
__device__ __align__(16) bf16 g_mAhi[MSM*DD], g_mAlo[MSM*DD];
__device__ __align__(16) bf16 g_mBhi[MSM*DD], g_mBlo[MSM*DD];
__device__ __align__(16) bf16 g_imhi[MMEM*DD], g_imlo[MMEM*DD];
__device__ __align__(16) bf16 g_wqhi[MMEM*DD], g_wqlo[MMEM*DD];

#define OW_QR (0LL*WMAT)
#define OW_KR (1LL*WMAT)
#define OW_VR (2LL*WMAT)
#define OW_OR (3LL*WMAT)
#define OW_GR (4LL*WMAT)
#define OW_QW (5LL*WMAT)
#define OW_KW (6LL*WMAT)
#define OW_VW (7LL*WMAT)
#define OW_OW (8LL*WMAT)
#define OW_GW (9LL*WMAT)

__device__ __forceinline__ void cp16(uint32_t s, const void* g) {
    asm volatile("cp.async.cg.shared.global [%0], [%1], 16;\n" :: "r"(s), "l"(g));
}
__device__ __forceinline__ void ldsm4(uint32_t& r0, uint32_t& r1, uint32_t& r2,
                                      uint32_t& r3, uint32_t a) {
    asm volatile("ldmatrix.sync.aligned.m8n8.x4.shared.b16 {%0,%1,%2,%3}, [%4];"
                 : "=r"(r0), "=r"(r1), "=r"(r2), "=r"(r3) : "r"(a));
}
__device__ __forceinline__ void ldsm4t(uint32_t& r0, uint32_t& r1, uint32_t& r2,
                                       uint32_t& r3, uint32_t a) {
    asm volatile("ldmatrix.sync.aligned.m8n8.x4.trans.shared.b16 {%0,%1,%2,%3}, [%4];"
                 : "=r"(r0), "=r"(r1), "=r"(r2), "=r"(r3) : "r"(a));
}
__device__ __forceinline__ void mma16816(float* c, const uint32_t* a, const uint32_t* b) {
    asm volatile("mma.sync.aligned.m16n8k16.row.col.f32.bf16.bf16.f32 "
                 "{%0,%1,%2,%3}, {%4,%5,%6,%7}, {%8,%9}, {%0,%1,%2,%3};"
                 : "+f"(c[0]), "+f"(c[1]), "+f"(c[2]), "+f"(c[3])
                 : "r"(a[0]), "r"(a[1]), "r"(a[2]), "r"(a[3]), "r"(b[0]), "r"(b[1]));
}
__device__ __forceinline__ float sig_(float x) { return 1.0f / (1.0f + __expf(-x)); }

// ---- bf16-split HMMA GEMM: C = (Ah+Al)@Wh + Ah@Wl, fp32 accumulate --------
// BM x 160 block tile; 4 row-warps x 2 col-warps; WM = MT*16, WN = 80.
// Inner loop consumes B in 5 groups of 16 cols to keep live regs <= 128.
template<int BM, int MT, int EPI, bool SPLIT>
__global__ void __launch_bounds__(256, 2)
mma_gemm(const bf16* __restrict__ Ah, const bf16* __restrict__ Al,
         const bf16* __restrict__ Wh, const bf16* __restrict__ Wl,
         float* __restrict__ C, bf16* __restrict__ Shi, bf16* __restrict__ Slo,
         int N, int K, int a_cr, long long a_cs, int c_cr, long long c_cs,
         const float* __restrict__ aux0, const float* __restrict__ aux1,
         const float* __restrict__ aux2) {
    constexpr int WM = MT * 16;
    constexpr int A_ROWB = BKT * 2 + 16;          // 80B
    constexpr int B_ROWB = BN * 2 + 16;           // 336B
    constexpr int A_TILE = BM * A_ROWB;
    constexpr int B_TILE = BKT * B_ROWB;
    constexpr int STAGE = 2 * A_TILE + 2 * B_TILE;

    extern __shared__ char smem_raw[];
    const uint32_t sbase = (uint32_t)__cvta_generic_to_shared(smem_raw);

    const int tid = threadIdx.x;
    const int m0 = blockIdx.y * BM, n0 = blockIdx.x * BN;
    const int warp = tid >> 5, lane = tid & 31;
    const int wid_m = warp >> 1, wid_n = warp & 1;
    const long long arow0 = (long long)(m0 / a_cr) * a_cs + (m0 % a_cr);

    float acc[MT][NT][4];
#pragma unroll
    for (int i = 0; i < MT; ++i)
#pragma unroll
        for (int j = 0; j < NT; ++j)
#pragma unroll
            for (int e = 0; e < 4; ++e) acc[i][j][e] = 0.0f;

    const int NKI = K / BKT;

    auto ldst = [&](int ks, int st) {
        const int k0 = ks * BKT;
        const uint32_t sb = sbase + st * STAGE;
#pragma unroll
        for (int t = 0; t < (BM * 4) / 256; ++t) {
            const int c = tid + t * 256;
            const int r = c >> 2, kc = (c & 3) * 8;
            const uint32_t off = r * A_ROWB + kc * 2;
            const long long gi = (arow0 + r) * (long long)K + k0 + kc;
            cp16(sb + off, Ah + gi);
            cp16(sb + A_TILE + off, Al + gi);
        }
        for (int c = tid; c < 640; c += 256) {
            const int r = c / 20, nc = c % 20;
            const uint32_t off = 2 * A_TILE + r * B_ROWB + nc * 16;
            const long long gi = (long long)(k0 + r) * N + n0 + nc * 8;
            cp16(sb + off, Wh + gi);
            cp16(sb + B_TILE + off, Wl + gi);
        }
        asm volatile("cp.async.commit_group;\n");
    };

    ldst(0, 0);
    ldst(1, 1);

    for (int ks = 0; ks < NKI; ++ks) {
        if (ks < NKI - 1) asm volatile("cp.async.wait_group 1;\n");
        else              asm volatile("cp.async.wait_group 0;\n");
        __syncthreads();
        const uint32_t sb = sbase + (ks & 1) * STAGE;

#pragma unroll
        for (int kk = 0; kk < BKT; kk += 16) {
            uint32_t ah[MT][4], al[MT][4];
            const int arow = wid_m * WM + (lane & 15);
            const int acol = kk + (lane >> 4) * 8;
#pragma unroll
            for (int i = 0; i < MT; ++i) {
                const uint32_t ad = sb + (arow + i * 16) * A_ROWB + acol * 2;
                ldsm4(ah[i][0], ah[i][1], ah[i][2], ah[i][3], ad);
                ldsm4(al[i][0], al[i][1], al[i][2], al[i][3], ad + A_TILE);
            }
            const int brow = kk + (lane & 15);
            const uint32_t bbase = sb + 2 * A_TILE + brow * B_ROWB
                                 + (wid_n * WN + (lane >> 4) * 8) * 2;
            // consume B in 5 groups of 16 columns; only 8 B-regs live at once
#pragma unroll
            for (int g = 0; g < 5; ++g) {
                uint32_t bh[4], bl[4];
                ldsm4t(bh[0], bh[1], bh[2], bh[3], bbase + g * 32);
                ldsm4t(bl[0], bl[1], bl[2], bl[3], bbase + B_TILE + g * 32);
#pragma unroll
                for (int i = 0; i < MT; ++i) {
                    mma16816(acc[i][2*g],   ah[i], bh);
                    mma16816(acc[i][2*g+1], ah[i], bh + 2);
                    mma16816(acc[i][2*g],   al[i], bh);
                    mma16816(acc[i][2*g+1], al[i], bh + 2);
                    mma16816(acc[i][2*g],   ah[i], bl);
                    mma16816(acc[i][2*g+1], ah[i], bl + 2);
                }
            }
        }
        __syncthreads();
        if (ks + 2 < NKI) ldst(ks + 2, ks & 1);
    }

    const int gid = lane >> 2, tig = lane & 3;
    const long long crow0 = (long long)(m0 / c_cr) * c_cs + (m0 % c_cr);

#pragma unroll
    for (int i = 0; i < MT; ++i) {
        const int r = wid_m * WM + i * 16 + gid;
#pragma unroll
        for (int j = 0; j < NT; ++j) {
            const int col = n0 + wid_n * WN + j * 8 + 2 * tig;
#pragma unroll
            for (int half = 0; half < 2; ++half) {
                const int rr = r + half * 8;
                const long long ci = (crow0 + rr) * (long long)N + col;
                const long long li = (long long)(m0 + rr) * N + col;
                float2 v;
#pragma unroll
                for (int e = 0; e < 2; ++e) {
                    const float a = acc[i][j][2 * half + e];
                    float o;
                    if      (EPI == 0) o = a;
                    else if (EPI == 1) o = sig_(a + aux0[col + e]);
                    else if (EPI == 2) o = aux1[ci + e] + aux2[li + e] * a;
                    else { const float s = sig_(a + aux0[col + e]);
                           o = s * aux1[li + e] + (1.0f - s) * aux2[li + e]; }
                    (&v.x)[e] = o;
                }
                *reinterpret_cast<float2*>(C + ci) = v;
                if (SPLIT) {
                    const bf16 h0 = __float2bfloat16(v.x), h1 = __float2bfloat16(v.y);
                    *reinterpret_cast<__nv_bfloat162*>(Shi + li) = __nv_bfloat162(h0, h1);
                    *reinterpret_cast<__nv_bfloat162*>(Slo + li) = __nv_bfloat162(
                        __float2bfloat16(v.x - __bfloat162float(h0)),
                        __float2bfloat16(v.y - __bfloat162float(h1)));
                }
            }
        }
    }
}

// ---- flash attention: 16 queries/block, warp w owns queries 2w, 2w+1 -------
__global__ void __launch_bounds__(256)
attn16(const float* __restrict__ Q, const float* __restrict__ Kp,
       const float* __restrict__ V, bf16* __restrict__ Ohi, bf16* __restrict__ Olo,
       int Lq, int Lk, float scale) {
    __shared__ float Ks[16][HDIM], Vs[16][HDIM];
    const int h = blockIdx.y, b = blockIdx.z, q0 = blockIdx.x * 16;
    const int tid = threadIdx.x, w = tid >> 5, l = tid & 31;
    const int qa = q0 + 2 * w;

    float qA[10], qB[10];
    const float* Qb = Q + ((long long)(b * Lq + qa)) * DD + h * HDIM;
#pragma unroll
    for (int t = 0; t < 10; ++t) { qA[t] = Qb[l + 32 * t]; qB[t] = Qb[DD + l + 32 * t]; }

    float mrun = -1e30f, sA = 0.0f, sB = 0.0f, accA[10], accB[10];
#pragma unroll
    for (int t = 0; t < 10; ++t) { accA[t] = 0.0f; accB[t] = 0.0f; }

    for (int c = 0; c < Lk / 16; ++c) {
        const long long k0 = (long long)(b * Lk + c * 16) * DD + h * HDIM;
#pragma unroll
        for (int t = 0; t < 5; ++t) {
            const int idx = tid + t * 256;
            const int row = idx / 80, c4 = idx % 80;
            *reinterpret_cast<float4*>(&Ks[row][c4 * 4]) =
                *reinterpret_cast<const float4*>(Kp + k0 + (long long)row * DD + c4 * 4);
            *reinterpret_cast<float4*>(&Vs[row][c4 * 4]) =
                *reinterpret_cast<const float4*>(V + k0 + (long long)row * DD + c4 * 4);
        }
        __syncthreads();
        float scA[16], scB[16], cmax = -1e30f;
#pragma unroll
        for (int k = 0; k < 16; ++k) {
            float da = 0.0f, db = 0.0f;
#pragma unroll
            for (int t = 0; t < 10; ++t) {
                const float kv = Ks[k][l + 32 * t];
                da += qA[t] * kv; db += qB[t] * kv;
            }
#pragma unroll
            for (int o = 16; o > 0; o >>= 1) {
                da += __shfl_xor_sync(0xFFFFFFFF, da, o);
                db += __shfl_xor_sync(0xFFFFFFFF, db, o);
            }
            scA[k] = da * scale; scB[k] = db * scale;
            cmax = fmaxf(cmax, fmaxf(scA[k], scB[k]));
        }
        const float mn = fmaxf(mrun, cmax);
        const float cr = __expf(mrun - mn);
        sA *= cr; sB *= cr;
#pragma unroll
        for (int t = 0; t < 10; ++t) { accA[t] *= cr; accB[t] *= cr; }
        mrun = mn;
#pragma unroll
        for (int k = 0; k < 16; ++k) {
            const float pa = __expf(scA[k] - mn), pb = __expf(scB[k] - mn);
            sA += pa; sB += pb;
#pragma unroll
            for (int t = 0; t < 10; ++t) {
                const float vv = Vs[k][l + 32 * t];
                accA[t] += pa * vv; accB[t] += pb * vv;
            }
        }
        __syncthreads();
    }
    const float iA = 1.0f / sA, iB = 1.0f / sB;
    bf16* Oh = Ohi + ((long long)(b * Lq + qa)) * DD + h * HDIM;
    bf16* Ol = Olo + ((long long)(b * Lq + qa)) * DD + h * HDIM;
#pragma unroll
    for (int t = 0; t < 10; ++t) {
        const float va = accA[t] * iA, vb = accB[t] * iB;
        const bf16 ha = __float2bfloat16(va), hb = __float2bfloat16(vb);
        Oh[l + 32 * t] = ha;      Ol[l + 32 * t] = __float2bfloat16(va - __bfloat162float(ha));
        Oh[DD + l + 32 * t] = hb; Ol[DD + l + 32 * t] = __float2bfloat16(vb - __bfloat162float(hb));
    }
}

struct WSrc { const float* p[11]; };

__global__ void wsplit_all(WSrc ws, bf16* __restrict__ hi, bf16* __restrict__ lo) {
    const int mat = blockIdx.y;
    const long long o = (long long)mat * WMAT + (long long)blockIdx.x * 256 + threadIdx.x;
    const float v = ws.p[mat][(long long)blockIdx.x * 256 + threadIdx.x];
    const bf16 h = __float2bfloat16(v);
    hi[o] = h; lo[o] = __float2bfloat16(v - __bfloat162float(h));
}

__global__ void split_id(const float* __restrict__ x, bf16* __restrict__ hi,
                         bf16* __restrict__ lo) {
    const long long o = (long long)blockIdx.x * 256 + threadIdx.x;
    const float v = x[o];
    const bf16 h = __float2bfloat16(v);
    hi[o] = h; lo[o] = __float2bfloat16(v - __bfloat162float(h));
}

__global__ void concat_split(const float* __restrict__ mem, const float* __restrict__ nm,
                             bf16* __restrict__ hi, bf16* __restrict__ lo) {
    const long long idx = (long long)blockIdx.x * 256 + threadIdx.x;
    const long long r = idx / (2 * DD);
    const int c = (int)(idx % (2 * DD));
    const float v = (c < DD) ? mem[r * DD + c] : nm[r * DD + c - DD];
    const bf16 h = __float2bfloat16(v);
    hi[idx] = h; lo[idx] = __float2bfloat16(v - __bfloat162float(h));
}

extern "C" void kernel_launch(void* const* d_in, const int* in_sizes, int n_in,
                              void* d_out, int out_size) {
    const float* hid      = (const float*)d_in[0];
    const float* init_mem = (const float*)d_in[1];
    const float* wq_r = (const float*)d_in[2];
    const float* wk_r = (const float*)d_in[3];
    const float* wv_r = (const float*)d_in[4];
    const float* wo_r = (const float*)d_in[5];
    const float* wg_r = (const float*)d_in[6];
    const float* bg_r = (const float*)d_in[7];
    const float* wqueries = (const float*)d_in[8];
    const float* wq_w = (const float*)d_in[9];
    const float* wk_w = (const float*)d_in[10];
    const float* wv_w = (const float*)d_in[11];
    const float* wo_w = (const float*)d_in[12];
    const float* wg_w = (const float*)d_in[13];
    const float* bg_w = (const float*)d_in[14];
    float* out = (float*)d_out;

    float *qr, *gate, *kw, *vw, *kr, *vr, *qw, *nm, *memA, *memB;
    bf16 *whi, *wlo, *hidhi, *hidlo, *chi, *clo, *ahi, *alo, *awhi, *awlo;
    bf16 *cathi, *catlo, *mAhi, *mAlo, *mBhi, *mBlo, *imhi, *imlo, *wqhi, *wqlo;
    cudaGetSymbolAddress((void**)&qr, g_qr);     cudaGetSymbolAddress((void**)&gate, g_gate);
    cudaGetSymbolAddress((void**)&kw, g_kw);     cudaGetSymbolAddress((void**)&vw, g_vw);
    cudaGetSymbolAddress((void**)&kr, g_kr);     cudaGetSymbolAddress((void**)&vr, g_vr);
    cudaGetSymbolAddress((void**)&qw, g_qw);     cudaGetSymbolAddress((void**)&nm, g_nm);
    cudaGetSymbolAddress((void**)&memA, g_memA); cudaGetSymbolAddress((void**)&memB, g_memB);
    cudaGetSymbolAddress((void**)&whi, g_whi);   cudaGetSymbolAddress((void**)&wlo, g_wlo);
    cudaGetSymbolAddress((void**)&hidhi, g_hidhi); cudaGetSymbolAddress((void**)&hidlo, g_hidlo);
    cudaGetSymbolAddress((void**)&chi, g_chi);   cudaGetSymbolAddress((void**)&clo, g_clo);
    cudaGetSymbolAddress((void**)&ahi, g_ahi);   cudaGetSymbolAddress((void**)&alo, g_alo);
    cudaGetSymbolAddress((void**)&awhi, g_awhi); cudaGetSymbolAddress((void**)&awlo, g_awlo);
    cudaGetSymbolAddress((void**)&cathi, g_cathi); cudaGetSymbolAddress((void**)&catlo, g_catlo);
    cudaGetSymbolAddress((void**)&mAhi, g_mAhi); cudaGetSymbolAddress((void**)&mAlo, g_mAlo);
    cudaGetSymbolAddress((void**)&mBhi, g_mBhi); cudaGetSymbolAddress((void**)&mBlo, g_mBlo);
    cudaGetSymbolAddress((void**)&imhi, g_imhi); cudaGetSymbolAddress((void**)&imlo, g_imlo);
    cudaGetSymbolAddress((void**)&wqhi, g_wqhi); cudaGetSymbolAddress((void**)&wqlo, g_wqlo);

    constexpr int SMEM_BIG = 2 * (2 * 128 * 80 + 2 * 32 * 336);   // 83968
    constexpr int SMEM_SM  = 2 * (2 * 64  * 80 + 2 * 32 * 336);   // 63488
    cudaFuncSetAttribute(mma_gemm<128,2,0,false>, cudaFuncAttributeMaxDynamicSharedMemorySize, SMEM_BIG);
    cudaFuncSetAttribute(mma_gemm<128,2,1,false>, cudaFuncAttributeMaxDynamicSharedMemorySize, SMEM_BIG);
    cudaFuncSetAttribute(mma_gemm<128,2,2,true >, cudaFuncAttributeMaxDynamicSharedMemorySize, SMEM_BIG);
    cudaFuncSetAttribute(mma_gemm<64,1,0,false>,  cudaFuncAttributeMaxDynamicSharedMemorySize, SMEM_SM);
    cudaFuncSetAttribute(mma_gemm<64,1,0,true >,  cudaFuncAttributeMaxDynamicSharedMemorySize, SMEM_SM);
    cudaFuncSetAttribute(mma_gemm<64,1,3,true >,  cudaFuncAttributeMaxDynamicSharedMemorySize, SMEM_SM);

    const float scale = 0.05590169943749474f;
    const size_t memBytesF = (size_t)MMEM * DD * sizeof(float);
    dim3 gBig(DD / BN, MBIG / 128);   // (16,16) = 256 blocks -> 1 wave
    dim3 gSm (DD / BN, MSM / 64);     // (16,4)
    dim3 gQw (DD / BN, 1);

    WSrc ws;
    ws.p[0] = wq_r; ws.p[1] = wk_r; ws.p[2] = wv_r; ws.p[3] = wo_r; ws.p[4] = wg_r;
    ws.p[5] = wq_w; ws.p[6] = wk_w; ws.p[7] = wv_w; ws.p[8] = wo_w;
    ws.p[9] = wg_w; ws.p[10] = wg_w + (long long)WMAT;
    wsplit_all<<<dim3(WMAT/256, 11), 256>>>(ws, whi, wlo);

    split_id<<<(BATCH*STOT*DD)/256,256>>>(hid, hidhi, hidlo);
    split_id<<<(MMEM*DD)/256,256>>>(init_mem, imhi, imlo);
    split_id<<<(MMEM*DD)/256,256>>>(wqueries, wqhi, wqlo);

    // qw = write_queries @ wq_w (M=128), duplicate for batch
    mma_gemm<128,2,0,false><<<gQw,256,SMEM_BIG>>>(wqhi, wqlo, whi+OW_QW, wlo+OW_QW,
        qw, nullptr, nullptr, DD, DD, MMEM, 0, MMEM, 0, nullptr, nullptr, nullptr);
    cudaMemcpyAsync(qw + (size_t)MMEM*DD, qw, memBytesF, cudaMemcpyDeviceToDevice, 0);

    float* memf[2] = {memA, memB};
    bf16*  memh[2] = {mAhi, mBhi};
    bf16*  meml[2] = {mAlo, mBlo};
    int cur = 0;

    for (int i = 0; i < NSEG; ++i) {
        const float* segp = hid + (long long)i * SEGL * DD;
        float* outp = out + (long long)i * SEGL * DD;
        const bf16* shi = hidhi + (long long)i * SEGL * DD;
        const bf16* slo = hidlo + (long long)i * SEGL * DD;

        mma_gemm<128,2,0,false><<<gBig,256,SMEM_BIG>>>(shi, slo, whi+OW_QR, wlo+OW_QR,
            qr, nullptr, nullptr, DD, DD, SEGL, (long long)STOT, MBIG, 0, nullptr, nullptr, nullptr);
        mma_gemm<128,2,1,false><<<gBig,256,SMEM_BIG>>>(shi, slo, whi+OW_GR, wlo+OW_GR,
            gate, nullptr, nullptr, DD, DD, SEGL, (long long)STOT, MBIG, 0, bg_r, nullptr, nullptr);

        const bf16* mh = (i == 0) ? imhi : memh[cur];
        const bf16* ml = (i == 0) ? imlo : meml[cur];
        const int mcr = (i == 0) ? MMEM : MSM;
        mma_gemm<64,1,0,false><<<gSm,256,SMEM_SM>>>(mh, ml, whi+OW_KR, wlo+OW_KR,
            kr, nullptr, nullptr, DD, DD, mcr, 0, MSM, 0, nullptr, nullptr, nullptr);
        mma_gemm<64,1,0,false><<<gSm,256,SMEM_SM>>>(mh, ml, whi+OW_VR, wlo+OW_VR,
            vr, nullptr, nullptr, DD, DD, mcr, 0, MSM, 0, nullptr, nullptr, nullptr);

        attn16<<<dim3(SEGL/16, NH, BATCH),256>>>(qr, kr, vr, chi, clo, SEGL, MMEM, scale);

        mma_gemm<128,2,2,true><<<gBig,256,SMEM_BIG>>>(chi, clo, whi+OW_OR, wlo+OW_OR,
            outp, ahi, alo, DD, DD, MBIG, 0, SEGL, (long long)STOT, nullptr, segp, gate);

        mma_gemm<128,2,0,false><<<gBig,256,SMEM_BIG>>>(ahi, alo, whi+OW_KW, wlo+OW_KW,
            kw, nullptr, nullptr, DD, DD, MBIG, 0, MBIG, 0, nullptr, nullptr, nullptr);
        mma_gemm<128,2,0,false><<<gBig,256,SMEM_BIG>>>(ahi, alo, whi+OW_VW, wlo+OW_VW,
            vw, nullptr, nullptr, DD, DD, MBIG, 0, MBIG, 0, nullptr, nullptr, nullptr);

        attn16<<<dim3(MMEM/16, NH, BATCH),256>>>(qw, kw, vw, awhi, awlo, MMEM, SEGL, scale);

        if (i == 0) {
            mma_gemm<64,1,0,true><<<gSm,256,SMEM_SM>>>(awhi, awlo, whi+OW_OW, wlo+OW_OW,
                memf[0], mAhi, mAlo, DD, DD, MSM, 0, MSM, 0, nullptr, nullptr, nullptr);
            cur = 0;
        } else {
            mma_gemm<64,1,0,false><<<gSm,256,SMEM_SM>>>(awhi, awlo, whi+OW_OW, wlo+OW_OW,
                nm, nullptr, nullptr, DD, DD, MSM, 0, MSM, 0, nullptr, nullptr, nullptr);
            const int nxt = cur ^ 1;
            concat_split<<<(MSM*2*DD)/256,256>>>(memf[cur], nm, cathi, catlo);
            mma_gemm<64,1,3,true><<<gSm,256,SMEM_SM>>>(cathi, catlo, whi+OW_GW, wlo+OW_GW,
                memf[nxt], memh[nxt], meml[nxt], DD, 2*DD, MSM, 0, MSM, 0,
                bg_w, nm, memf[cur]);
            cur = nxt;
        }
    }
}

// round 9
// speedup vs baseline: 1.1160x; 1.1160x over previous
#include <cuda_runtime.h>
#include <cuda_bf16.h>
#include <math.h>
#include <stdint.h>
typedef __nv_bfloat16 bf16;

#define DD    2560
#define HDIM  320
#define NH    8
#define SEGL  1024
#define STOT  4096
#define BATCH 2
#define MMEM  128
#define NSEG  4
#define MBIG  (BATCH*SEGL)
#define MSM   (BATCH*MMEM)
#define BKT   32

// fp32 scratch
__device__ float g_qr[MBIG*DD], g_gate[MBIG*DD], g_kw[MBIG*DD], g_vw[MBIG*DD];
__device__ float g_kr[MSM*DD], g_vr[MSM*DD], g_qw[MSM*DD], g_nm[MSM*DD];
__device__ float g_memA[MSM*DD], g_memB[MSM*DD];
// bf16 scratch
#define WMAT (DD*DD)
__device__ __align__(16) bf16 g_whi[11LL*WMAT], g_wlo[11LL*WMAT];
__device__ __align__(16) bf16 g_hidhi[BATCH*STOT*DD], g_hidlo[BATCH*STOT*DD];
__device__ __align__(16) bf16 g_chi[MBIG*DD], g_clo[MBIG*DD];
__device__ __align__(16) bf16 g_ahi[MBIG*DD], g_alo[MBIG*DD];
__device__ __align__(16) bf16 g_awhi[MSM*DD], g_awlo[MSM*DD];
__device__ __align__(16) bf16 g_cathi[MSM*2*DD], g_catlo[MSM*2*DD];
__device__ __align__(16) bf16 g_mAhi[MSM*DD], g_mAlo[MSM*DD];
__device__ __align__(16) bf16 g_mBhi[MSM*DD], g_mBlo[MSM*DD];
__device__ __align__(16) bf16 g_imhi[MMEM*DD], g_imlo[MMEM*DD];
__device__ __align__(16) bf16 g_wqhi[MMEM*DD], g_wqlo[MMEM*DD];

#define OW_QR (0LL*WMAT)
#define OW_KR (1LL*WMAT)
#define OW_VR (2LL*WMAT)
#define OW_OR (3LL*WMAT)
#define OW_GR (4LL*WMAT)
#define OW_QW (5LL*WMAT)
#define OW_KW (6LL*WMAT)
#define OW_VW (7LL*WMAT)
#define OW_OW (8LL*WMAT)
#define OW_GW (9LL*WMAT)

__device__ __forceinline__ void cp16(uint32_t s, const void* g) {
    asm volatile("cp.async.cg.shared.global [%0], [%1], 16;\n" :: "r"(s), "l"(g));
}
__device__ __forceinline__ void ldsm4(uint32_t& r0, uint32_t& r1, uint32_t& r2,
                                      uint32_t& r3, uint32_t a) {
    asm volatile("ldmatrix.sync.aligned.m8n8.x4.shared.b16 {%0,%1,%2,%3}, [%4];"
                 : "=r"(r0), "=r"(r1), "=r"(r2), "=r"(r3) : "r"(a));
}
__device__ __forceinline__ void ldsm4t(uint32_t& r0, uint32_t& r1, uint32_t& r2,
                                       uint32_t& r3, uint32_t a) {
    asm volatile("ldmatrix.sync.aligned.m8n8.x4.trans.shared.b16 {%0,%1,%2,%3}, [%4];"
                 : "=r"(r0), "=r"(r1), "=r"(r2), "=r"(r3) : "r"(a));
}
__device__ __forceinline__ void mma16816(float* c, const uint32_t* a, const uint32_t* b) {
    asm volatile("mma.sync.aligned.m16n8k16.row.col.f32.bf16.bf16.f32 "
                 "{%0,%1,%2,%3}, {%4,%5,%6,%7}, {%8,%9}, {%0,%1,%2,%3};"
                 : "+f"(c[0]), "+f"(c[1]), "+f"(c[2]), "+f"(c[3])
                 : "r"(a[0]), "r"(a[1]), "r"(a[2]), "r"(a[3]), "r"(b[0]), "r"(b[1]));
}
__device__ __forceinline__ float sig_(float x) { return 1.0f / (1.0f + __expf(-x)); }

// ---- bf16-split HMMA GEMM: C = (Ah+Al)@Wh + Ah@Wl, fp32 accumulate --------
// Block tile BM x BN_. 8 warps as 4 rows x 2 cols. WM=MT*16, WN=NT_*8.
template<int BM, int BN_, int MT, int NT_, int EPI, bool SPLIT>
__global__ void __launch_bounds__(256, 2)
mma_gemm(const bf16* __restrict__ Ah, const bf16* __restrict__ Al,
         const bf16* __restrict__ Wh, const bf16* __restrict__ Wl,
         float* __restrict__ C, bf16* __restrict__ Shi, bf16* __restrict__ Slo,
         int N, int K, int a_cr, long long a_cs, int c_cr, long long c_cs,
         const float* __restrict__ aux0, const float* __restrict__ aux1,
         const float* __restrict__ aux2) {
    constexpr int WM = MT * 16, WN = NT_ * 8;
    constexpr int A_ROWB = BKT * 2 + 16;
    constexpr int B_ROWB = BN_ * 2 + 16;
    constexpr int A_TILE = BM * A_ROWB;
    constexpr int B_TILE = BKT * B_ROWB;
    constexpr int STAGE = 2 * A_TILE + 2 * B_TILE;
    constexpr int BCH = BN_ / 8;

    extern __shared__ char smem_raw[];
    const uint32_t sbase = (uint32_t)__cvta_generic_to_shared(smem_raw);

    const int tid = threadIdx.x;
    const int m0 = blockIdx.y * BM, n0 = blockIdx.x * BN_;
    const int warp = tid >> 5, lane = tid & 31;
    const int wid_m = warp >> 1, wid_n = warp & 1;
    const long long arow0 = (long long)(m0 / a_cr) * a_cs + (m0 % a_cr);

    float acc[MT][NT_][4];
#pragma unroll
    for (int i = 0; i < MT; ++i)
#pragma unroll
        for (int j = 0; j < NT_; ++j)
#pragma unroll
            for (int e = 0; e < 4; ++e) acc[i][j][e] = 0.0f;

    const int NKI = K / BKT;

    auto ldst = [&](int ks, int st) {
        const int k0 = ks * BKT;
        const uint32_t sb = sbase + st * STAGE;
#pragma unroll
        for (int t = 0; t < (BM * 4) / 256; ++t) {
            const int c = tid + t * 256;
            const int r = c >> 2, kc = (c & 3) * 8;
            const uint32_t off = r * A_ROWB + kc * 2;
            const long long gi = (arow0 + r) * (long long)K + k0 + kc;
            cp16(sb + off, Ah + gi);
            cp16(sb + A_TILE + off, Al + gi);
        }
        for (int c = tid; c < 4 * BN_; c += 256) {
            const int r = c / BCH, nc = c % BCH;
            const uint32_t off = 2 * A_TILE + r * B_ROWB + nc * 16;
            const long long gi = (long long)(k0 + r) * N + n0 + nc * 8;
            cp16(sb + off, Wh + gi);
            cp16(sb + B_TILE + off, Wl + gi);
        }
        asm volatile("cp.async.commit_group;\n");
    };

    ldst(0, 0);
    ldst(1, 1);

    for (int ks = 0; ks < NKI; ++ks) {
        if (ks < NKI - 1) asm volatile("cp.async.wait_group 1;\n");
        else              asm volatile("cp.async.wait_group 0;\n");
        __syncthreads();
        const uint32_t sb = sbase + (ks & 1) * STAGE;

#pragma unroll
        for (int kk = 0; kk < BKT; kk += 16) {
            uint32_t ah[MT][4], al[MT][4], b[NT_][2];
            const int arow = wid_m * WM + (lane & 15);
            const int acol = kk + (lane >> 4) * 8;
#pragma unroll
            for (int i = 0; i < MT; ++i) {
                const uint32_t ad = sb + (arow + i * 16) * A_ROWB + acol * 2;
                ldsm4(ah[i][0], ah[i][1], ah[i][2], ah[i][3], ad);
                ldsm4(al[i][0], al[i][1], al[i][2], al[i][3], ad + A_TILE);
            }
            const int brow = kk + (lane & 15);
            const uint32_t bbase = sb + 2 * A_TILE + brow * B_ROWB;
#pragma unroll
            for (int j2 = 0; j2 < NT_ / 2; ++j2) {
                const int bcol = wid_n * WN + j2 * 16 + (lane >> 4) * 8;
                ldsm4t(b[2*j2][0], b[2*j2][1], b[2*j2+1][0], b[2*j2+1][1],
                       bbase + bcol * 2);
            }
#pragma unroll
            for (int i = 0; i < MT; ++i)
#pragma unroll
                for (int j = 0; j < NT_; ++j) {
                    mma16816(acc[i][j], ah[i], b[j]);
                    mma16816(acc[i][j], al[i], b[j]);
                }
#pragma unroll
            for (int j2 = 0; j2 < NT_ / 2; ++j2) {
                const int bcol = wid_n * WN + j2 * 16 + (lane >> 4) * 8;
                ldsm4t(b[2*j2][0], b[2*j2][1], b[2*j2+1][0], b[2*j2+1][1],
                       bbase + B_TILE + bcol * 2);
            }
#pragma unroll
            for (int i = 0; i < MT; ++i)
#pragma unroll
                for (int j = 0; j < NT_; ++j)
                    mma16816(acc[i][j], ah[i], b[j]);
        }
        __syncthreads();
        if (ks + 2 < NKI) ldst(ks + 2, ks & 1);
    }

    const int gid = lane >> 2, tig = lane & 3;
    const long long crow0 = (long long)(m0 / c_cr) * c_cs + (m0 % c_cr);

#pragma unroll
    for (int i = 0; i < MT; ++i) {
        const int r = wid_m * WM + i * 16 + gid;
#pragma unroll
        for (int j = 0; j < NT_; ++j) {
            const int col = n0 + wid_n * WN + j * 8 + 2 * tig;
#pragma unroll
            for (int half = 0; half < 2; ++half) {
                const int rr = r + half * 8;
                const long long ci = (crow0 + rr) * (long long)N + col;
                const long long li = (long long)(m0 + rr) * N + col;
                float2 v;
#pragma unroll
                for (int e = 0; e < 2; ++e) {
                    const float a = acc[i][j][2 * half + e];
                    float o;
                    if      (EPI == 0) o = a;
                    else if (EPI == 1) o = sig_(a + aux0[col + e]);
                    else if (EPI == 2) o = aux1[ci + e] + aux2[li + e] * a;
                    else { const float s = sig_(a + aux0[col + e]);
                           o = s * aux1[li + e] + (1.0f - s) * aux2[li + e]; }
                    (&v.x)[e] = o;
                }
                *reinterpret_cast<float2*>(C + ci) = v;
                if (SPLIT) {
                    const bf16 h0 = __float2bfloat16(v.x), h1 = __float2bfloat16(v.y);
                    *reinterpret_cast<__nv_bfloat162*>(Shi + li) = __nv_bfloat162(h0, h1);
                    *reinterpret_cast<__nv_bfloat162*>(Slo + li) = __nv_bfloat162(
                        __float2bfloat16(v.x - __bfloat162float(h0)),
                        __float2bfloat16(v.y - __bfloat162float(h1)));
                }
            }
        }
    }
}

// ---- flash attention: 16 queries/block, warp w owns queries 2w, 2w+1 -------
__global__ void __launch_bounds__(256)
attn16(const float* __restrict__ Q, const float* __restrict__ Kp,
       const float* __restrict__ V, bf16* __restrict__ Ohi, bf16* __restrict__ Olo,
       int Lq, int Lk, float scale) {
    __shared__ float Ks[16][HDIM], Vs[16][HDIM];
    const int h = blockIdx.y, b = blockIdx.z, q0 = blockIdx.x * 16;
    const int tid = threadIdx.x, w = tid >> 5, l = tid & 31;
    const int qa = q0 + 2 * w;

    float qA[10], qB[10];
    const float* Qb = Q + ((long long)(b * Lq + qa)) * DD + h * HDIM;
#pragma unroll
    for (int t = 0; t < 10; ++t) { qA[t] = Qb[l + 32 * t]; qB[t] = Qb[DD + l + 32 * t]; }

    float mrun = -1e30f, sA = 0.0f, sB = 0.0f, accA[10], accB[10];
#pragma unroll
    for (int t = 0; t < 10; ++t) { accA[t] = 0.0f; accB[t] = 0.0f; }

    for (int c = 0; c < Lk / 16; ++c) {
        const long long k0 = (long long)(b * Lk + c * 16) * DD + h * HDIM;
#pragma unroll
        for (int t = 0; t < 5; ++t) {
            const int idx = tid + t * 256;
            const int row = idx / 80, c4 = idx % 80;
            *reinterpret_cast<float4*>(&Ks[row][c4 * 4]) =
                *reinterpret_cast<const float4*>(Kp + k0 + (long long)row * DD + c4 * 4);
            *reinterpret_cast<float4*>(&Vs[row][c4 * 4]) =
                *reinterpret_cast<const float4*>(V + k0 + (long long)row * DD + c4 * 4);
        }
        __syncthreads();
        float scA[16], scB[16], cmax = -1e30f;
#pragma unroll
        for (int k = 0; k < 16; ++k) {
            float da = 0.0f, db = 0.0f;
#pragma unroll
            for (int t = 0; t < 10; ++t) {
                const float kv = Ks[k][l + 32 * t];
                da += qA[t] * kv; db += qB[t] * kv;
            }
#pragma unroll
            for (int o = 16; o > 0; o >>= 1) {
                da += __shfl_xor_sync(0xFFFFFFFF, da, o);
                db += __shfl_xor_sync(0xFFFFFFFF, db, o);
            }
            scA[k] = da * scale; scB[k] = db * scale;
            cmax = fmaxf(cmax, fmaxf(scA[k], scB[k]));
        }
        const float mn = fmaxf(mrun, cmax);
        const float cr = __expf(mrun - mn);
        sA *= cr; sB *= cr;
#pragma unroll
        for (int t = 0; t < 10; ++t) { accA[t] *= cr; accB[t] *= cr; }
        mrun = mn;
#pragma unroll
        for (int k = 0; k < 16; ++k) {
            const float pa = __expf(scA[k] - mn), pb = __expf(scB[k] - mn);
            sA += pa; sB += pb;
#pragma unroll
            for (int t = 0; t < 10; ++t) {
                const float vv = Vs[k][l + 32 * t];
                accA[t] += pa * vv; accB[t] += pb * vv;
            }
        }
        __syncthreads();
    }
    const float iA = 1.0f / sA, iB = 1.0f / sB;
    bf16* Oh = Ohi + ((long long)(b * Lq + qa)) * DD + h * HDIM;
    bf16* Ol = Olo + ((long long)(b * Lq + qa)) * DD + h * HDIM;
#pragma unroll
    for (int t = 0; t < 10; ++t) {
        const float va = accA[t] * iA, vb = accB[t] * iB;
        const bf16 ha = __float2bfloat16(va), hb = __float2bfloat16(vb);
        Oh[l + 32 * t] = ha;      Ol[l + 32 * t] = __float2bfloat16(va - __bfloat162float(ha));
        Oh[DD + l + 32 * t] = hb; Ol[DD + l + 32 * t] = __float2bfloat16(vb - __bfloat162float(hb));
    }
}

struct WSrc { const float* p[11]; };

__global__ void wsplit_all(WSrc ws, bf16* __restrict__ hi, bf16* __restrict__ lo) {
    const int mat = blockIdx.y;
    const long long o = (long long)mat * WMAT + (long long)blockIdx.x * 256 + threadIdx.x;
    const float v = ws.p[mat][(long long)blockIdx.x * 256 + threadIdx.x];
    const bf16 h = __float2bfloat16(v);
    hi[o] = h; lo[o] = __float2bfloat16(v - __bfloat162float(h));
}

__global__ void split_id(const float* __restrict__ x, bf16* __restrict__ hi,
                         bf16* __restrict__ lo) {
    const long long o = (long long)blockIdx.x * 256 + threadIdx.x;
    const float v = x[o];
    const bf16 h = __float2bfloat16(v);
    hi[o] = h; lo[o] = __float2bfloat16(v - __bfloat162float(h));
}

__global__ void concat_split(const float* __restrict__ mem, const float* __restrict__ nm,
                             bf16* __restrict__ hi, bf16* __restrict__ lo) {
    const long long idx = (long long)blockIdx.x * 256 + threadIdx.x;
    const long long r = idx / (2 * DD);
    const int c = (int)(idx % (2 * DD));
    const float v = (c < DD) ? mem[r * DD + c] : nm[r * DD + c - DD];
    const bf16 h = __float2bfloat16(v);
    hi[idx] = h; lo[idx] = __float2bfloat16(v - __bfloat162float(h));
}

// ---- side streams for fork/join concurrency (created pre-main) -------------
struct SideStreams {
    cudaStream_t s1, s2;
    cudaEvent_t eA, eK, eG, eH, eV, e0, e1, eW;
    bool ok;
    SideStreams() {
        ok = cudaStreamCreateWithFlags(&s1, cudaStreamNonBlocking) == cudaSuccess &&
             cudaStreamCreateWithFlags(&s2, cudaStreamNonBlocking) == cudaSuccess &&
             cudaEventCreateWithFlags(&eA, cudaEventDisableTiming) == cudaSuccess &&
             cudaEventCreateWithFlags(&eK, cudaEventDisableTiming) == cudaSuccess &&
             cudaEventCreateWithFlags(&eG, cudaEventDisableTiming) == cudaSuccess &&
             cudaEventCreateWithFlags(&eH, cudaEventDisableTiming) == cudaSuccess &&
             cudaEventCreateWithFlags(&eV, cudaEventDisableTiming) == cudaSuccess &&
             cudaEventCreateWithFlags(&e0, cudaEventDisableTiming) == cudaSuccess &&
             cudaEventCreateWithFlags(&e1, cudaEventDisableTiming) == cudaSuccess &&
             cudaEventCreateWithFlags(&eW, cudaEventDisableTiming) == cudaSuccess;
    }
};
static SideStreams SS;

extern "C" void kernel_launch(void* const* d_in, const int* in_sizes, int n_in,
                              void* d_out, int out_size) {
    const float* hid      = (const float*)d_in[0];
    const float* init_mem = (const float*)d_in[1];
    const float* wq_r = (const float*)d_in[2];
    const float* wk_r = (const float*)d_in[3];
    const float* wv_r = (const float*)d_in[4];
    const float* wo_r = (const float*)d_in[5];
    const float* wg_r = (const float*)d_in[6];
    const float* bg_r = (const float*)d_in[7];
    const float* wqueries = (const float*)d_in[8];
    const float* wq_w = (const float*)d_in[9];
    const float* wk_w = (const float*)d_in[10];
    const float* wv_w = (const float*)d_in[11];
    const float* wo_w = (const float*)d_in[12];
    const float* wg_w = (const float*)d_in[13];
    const float* bg_w = (const float*)d_in[14];
    float* out = (float*)d_out;

    float *qr, *gate, *kw, *vw, *kr, *vr, *qw, *nm, *memA, *memB;
    bf16 *whi, *wlo, *hidhi, *hidlo, *chi, *clo, *ahi, *alo, *awhi, *awlo;
    bf16 *cathi, *catlo, *mAhi, *mAlo, *mBhi, *mBlo, *imhi, *imlo, *wqhi, *wqlo;
    cudaGetSymbolAddress((void**)&qr, g_qr);     cudaGetSymbolAddress((void**)&gate, g_gate);
    cudaGetSymbolAddress((void**)&kw, g_kw);     cudaGetSymbolAddress((void**)&vw, g_vw);
    cudaGetSymbolAddress((void**)&kr, g_kr);     cudaGetSymbolAddress((void**)&vr, g_vr);
    cudaGetSymbolAddress((void**)&qw, g_qw);     cudaGetSymbolAddress((void**)&nm, g_nm);
    cudaGetSymbolAddress((void**)&memA, g_memA); cudaGetSymbolAddress((void**)&memB, g_memB);
    cudaGetSymbolAddress((void**)&whi, g_whi);   cudaGetSymbolAddress((void**)&wlo, g_wlo);
    cudaGetSymbolAddress((void**)&hidhi, g_hidhi); cudaGetSymbolAddress((void**)&hidlo, g_hidlo);
    cudaGetSymbolAddress((void**)&chi, g_chi);   cudaGetSymbolAddress((void**)&clo, g_clo);
    cudaGetSymbolAddress((void**)&ahi, g_ahi);   cudaGetSymbolAddress((void**)&alo, g_alo);
    cudaGetSymbolAddress((void**)&awhi, g_awhi); cudaGetSymbolAddress((void**)&awlo, g_awlo);
    cudaGetSymbolAddress((void**)&cathi, g_cathi); cudaGetSymbolAddress((void**)&catlo, g_catlo);
    cudaGetSymbolAddress((void**)&mAhi, g_mAhi); cudaGetSymbolAddress((void**)&mAlo, g_mAlo);
    cudaGetSymbolAddress((void**)&mBhi, g_mBhi); cudaGetSymbolAddress((void**)&mBlo, g_mBlo);
    cudaGetSymbolAddress((void**)&imhi, g_imhi); cudaGetSymbolAddress((void**)&imlo, g_imlo);
    cudaGetSymbolAddress((void**)&wqhi, g_wqhi); cudaGetSymbolAddress((void**)&wqlo, g_wqlo);

    constexpr int SMEM_BIG = 2 * (2 * 128 * 80 + 2 * 32 * 336);   // 83968
    constexpr int SMEM_SM  = 2 * (2 * 64  * 80 + 2 * 32 * 144);   // 38912
    cudaFuncSetAttribute(mma_gemm<128,160,2,10,0,false>, cudaFuncAttributeMaxDynamicSharedMemorySize, SMEM_BIG);
    cudaFuncSetAttribute(mma_gemm<128,160,2,10,1,false>, cudaFuncAttributeMaxDynamicSharedMemorySize, SMEM_BIG);
    cudaFuncSetAttribute(mma_gemm<128,160,2,10,2,true >, cudaFuncAttributeMaxDynamicSharedMemorySize, SMEM_BIG);
    cudaFuncSetAttribute(mma_gemm<64,64,1,4,0,false>,    cudaFuncAttributeMaxDynamicSharedMemorySize, SMEM_SM);
    cudaFuncSetAttribute(mma_gemm<64,64,1,4,0,true >,    cudaFuncAttributeMaxDynamicSharedMemorySize, SMEM_SM);
    cudaFuncSetAttribute(mma_gemm<64,64,1,4,3,true >,    cudaFuncAttributeMaxDynamicSharedMemorySize, SMEM_SM);

    const float scale = 0.05590169943749474f;
    const size_t memBytesF = (size_t)MMEM * DD * sizeof(float);
    dim3 gBig(DD / 160, MBIG / 128);   // (16,16) = 256 blocks
    dim3 gSm (DD / 64,  MSM / 64);     // (40,4)  = 160 blocks
    dim3 gQw (DD / 64,  MMEM / 64);    // (40,2)

    const bool ok = SS.ok;
    cudaStream_t t1 = ok ? SS.s1 : 0;
    cudaStream_t t2 = ok ? SS.s2 : 0;

    // ---- prologue: weight/activation splits (forked) ----
    if (ok) { cudaEventRecord(SS.e0, 0); cudaStreamWaitEvent(t1, SS.e0, 0);
              cudaStreamWaitEvent(t2, SS.e0, 0); }
    WSrc ws;
    ws.p[0] = wq_r; ws.p[1] = wk_r; ws.p[2] = wv_r; ws.p[3] = wo_r; ws.p[4] = wg_r;
    ws.p[5] = wq_w; ws.p[6] = wk_w; ws.p[7] = wv_w; ws.p[8] = wo_w;
    ws.p[9] = wg_w; ws.p[10] = wg_w + (long long)WMAT;
    wsplit_all<<<dim3(WMAT/256, 11), 256, 0, 0>>>(ws, whi, wlo);
    split_id<<<(BATCH*STOT*DD)/256, 256, 0, t1>>>(hid, hidhi, hidlo);
    split_id<<<(MMEM*DD)/256, 256, 0, t2>>>(init_mem, imhi, imlo);
    split_id<<<(MMEM*DD)/256, 256, 0, t2>>>(wqueries, wqhi, wqlo);
    if (ok) { cudaEventRecord(SS.eW, 0); cudaStreamWaitEvent(t2, SS.eW, 0); }
    mma_gemm<64,64,1,4,0,false><<<gQw, 256, SMEM_SM, t2>>>(wqhi, wqlo,
        whi+OW_QW, wlo+OW_QW, qw, nullptr, nullptr, DD, DD, MMEM, 0, MMEM, 0,
        nullptr, nullptr, nullptr);
    cudaMemcpyAsync(qw + (size_t)MMEM*DD, qw, memBytesF, cudaMemcpyDeviceToDevice, t2);
    if (ok) { cudaEventRecord(SS.e1, t1); cudaStreamWaitEvent(0, SS.e1, 0); }

    float* memf[2] = {memA, memB};
    bf16*  memh[2] = {mAhi, mBhi};
    bf16*  meml[2] = {mAlo, mBlo};
    int cur = 0;

    for (int i = 0; i < NSEG; ++i) {
        const float* segp = hid + (long long)i * SEGL * DD;
        float* outp = out + (long long)i * SEGL * DD;
        const bf16* shi = hidhi + (long long)i * SEGL * DD;
        const bf16* slo = hidlo + (long long)i * SEGL * DD;

        if (ok) { cudaEventRecord(SS.eA, 0); cudaStreamWaitEvent(t1, SS.eA, 0);
                  cudaStreamWaitEvent(t2, SS.eA, 0); }
        mma_gemm<128,160,2,10,0,false><<<gBig, 256, SMEM_BIG, 0>>>(shi, slo,
            whi+OW_QR, wlo+OW_QR, qr, nullptr, nullptr, DD, DD,
            SEGL, (long long)STOT, MBIG, 0, nullptr, nullptr, nullptr);
        mma_gemm<128,160,2,10,1,false><<<gBig, 256, SMEM_BIG, t1>>>(shi, slo,
            whi+OW_GR, wlo+OW_GR, gate, nullptr, nullptr, DD, DD,
            SEGL, (long long)STOT, MBIG, 0, bg_r, nullptr, nullptr);

        const bf16* mh = (i == 0) ? imhi : memh[cur];
        const bf16* ml = (i == 0) ? imlo : meml[cur];
        const int mcr = (i == 0) ? MMEM : MSM;
        mma_gemm<64,64,1,4,0,false><<<gSm, 256, SMEM_SM, t2>>>(mh, ml,
            whi+OW_KR, wlo+OW_KR, kr, nullptr, nullptr, DD, DD,
            mcr, 0, MSM, 0, nullptr, nullptr, nullptr);
        mma_gemm<64,64,1,4,0,false><<<gSm, 256, SMEM_SM, t2>>>(mh, ml,
            whi+OW_VR, wlo+OW_VR, vr, nullptr, nullptr, DD, DD,
            mcr, 0, MSM, 0, nullptr, nullptr, nullptr);
        if (ok) { cudaEventRecord(SS.eK, t2); cudaStreamWaitEvent(0, SS.eK, 0); }

        attn16<<<dim3(SEGL/16, NH, BATCH), 256, 0, 0>>>(qr, kr, vr, chi, clo,
                                                        SEGL, MMEM, scale);
        if (ok) { cudaEventRecord(SS.eG, t1); cudaStreamWaitEvent(0, SS.eG, 0); }

        mma_gemm<128,160,2,10,2,true><<<gBig, 256, SMEM_BIG, 0>>>(chi, clo,
            whi+OW_OR, wlo+OW_OR, outp, ahi, alo, DD, DD,
            MBIG, 0, SEGL, (long long)STOT, nullptr, segp, gate);

        if (ok) { cudaEventRecord(SS.eH, 0); cudaStreamWaitEvent(t1, SS.eH, 0); }
        mma_gemm<128,160,2,10,0,false><<<gBig, 256, SMEM_BIG, 0>>>(ahi, alo,
            whi+OW_KW, wlo+OW_KW, kw, nullptr, nullptr, DD, DD,
            MBIG, 0, MBIG, 0, nullptr, nullptr, nullptr);
        mma_gemm<128,160,2,10,0,false><<<gBig, 256, SMEM_BIG, t1>>>(ahi, alo,
            whi+OW_VW, wlo+OW_VW, vw, nullptr, nullptr, DD, DD,
            MBIG, 0, MBIG, 0, nullptr, nullptr, nullptr);
        if (ok) { cudaEventRecord(SS.eV, t1); cudaStreamWaitEvent(0, SS.eV, 0); }

        attn16<<<dim3(MMEM/16, NH, BATCH), 256, 0, 0>>>(qw, kw, vw, awhi, awlo,
                                                        MMEM, SEGL, scale);

        if (i == 0) {
            mma_gemm<64,64,1,4,0,true><<<gSm, 256, SMEM_SM, 0>>>(awhi, awlo,
                whi+OW_OW, wlo+OW_OW, memf[0], mAhi, mAlo, DD, DD,
                MSM, 0, MSM, 0, nullptr, nullptr, nullptr);
            cur = 0;
        } else {
            mma_gemm<64,64,1,4,0,false><<<gSm, 256, SMEM_SM, 0>>>(awhi, awlo,
                whi+OW_OW, wlo+OW_OW, nm, nullptr, nullptr, DD, DD,
                MSM, 0, MSM, 0, nullptr, nullptr, nullptr);
            const int nxt = cur ^ 1;
            concat_split<<<(MSM*2*DD)/256, 256, 0, 0>>>(memf[cur], nm, cathi, catlo);
            mma_gemm<64,64,1,4,3,true><<<gSm, 256, SMEM_SM, 0>>>(cathi, catlo,
                whi+OW_GW, wlo+OW_GW, memf[nxt], memh[nxt], meml[nxt], DD, 2*DD,
                MSM, 0, MSM, 0, bg_w, nm, memf[cur]);
            cur = nxt;
        }
    }
}

// round 10
// speedup vs baseline: 1.1242x; 1.0073x over previous
#include <cuda_runtime.h>
#include <cuda_bf16.h>
#include <math.h>
#include <stdint.h>
typedef __nv_bfloat16 bf16;

#define DD    2560
#define HDIM  320
#define NH    8
#define SEGL  1024
#define STOT  4096
#define BATCH 2
#define MMEM  128
#define NSEG  4
#define MBIG  (BATCH*SEGL)
#define MSM   (BATCH*MMEM)
#define BKT   32

// fp32 scratch
__device__ float g_qr[MBIG*DD], g_gate[MBIG*DD], g_kw[MBIG*DD], g_vw[MBIG*DD];
__device__ float g_kr[MSM*DD], g_vr[MSM*DD], g_qw[MSM*DD], g_nm[MSM*DD];
__device__ float g_memA[MSM*DD], g_memB[MSM*DD];
// bf16 scratch
#define WMAT (DD*DD)
__device__ __align__(16) bf16 g_whi[11LL*WMAT], g_wlo[11LL*WMAT];
__device__ __align__(16) bf16 g_hidhi[BATCH*STOT*DD], g_hidlo[BATCH*STOT*DD];
__device__ __align__(16) bf16 g_chi[MBIG*DD], g_clo[MBIG*DD];
__device__ __align__(16) bf16 g_ahi[MBIG*DD], g_alo[MBIG*DD];
__device__ __align__(16) bf16 g_awhi[MSM*DD], g_awlo[MSM*DD];
__device__ __align__(16) bf16 g_cathi[MSM*2*DD], g_catlo[MSM*2*DD];
__device__ __align__(16) bf16 g_mAhi[MSM*DD], g_mAlo[MSM*DD];
__device__ __align__(16) bf16 g_mBhi[MSM*DD], g_mBlo[MSM*DD];
__device__ __align__(16) bf16 g_imhi[MMEM*DD], g_imlo[MMEM*DD];
__device__ __align__(16) bf16 g_wqhi[MMEM*DD], g_wqlo[MMEM*DD];

#define OW_QR (0LL*WMAT)
#define OW_KR (1LL*WMAT)
#define OW_VR (2LL*WMAT)
#define OW_OR (3LL*WMAT)
#define OW_GR (4LL*WMAT)
#define OW_QW (5LL*WMAT)
#define OW_KW (6LL*WMAT)
#define OW_VW (7LL*WMAT)
#define OW_OW (8LL*WMAT)
#define OW_GW (9LL*WMAT)

__device__ __forceinline__ void cp16(uint32_t s, const void* g) {
    asm volatile("cp.async.cg.shared.global [%0], [%1], 16;\n" :: "r"(s), "l"(g));
}
__device__ __forceinline__ void ldsm4(uint32_t& r0, uint32_t& r1, uint32_t& r2,
                                      uint32_t& r3, uint32_t a) {
    asm volatile("ldmatrix.sync.aligned.m8n8.x4.shared.b16 {%0,%1,%2,%3}, [%4];"
                 : "=r"(r0), "=r"(r1), "=r"(r2), "=r"(r3) : "r"(a));
}
__device__ __forceinline__ void ldsm4t(uint32_t& r0, uint32_t& r1, uint32_t& r2,
                                       uint32_t& r3, uint32_t a) {
    asm volatile("ldmatrix.sync.aligned.m8n8.x4.trans.shared.b16 {%0,%1,%2,%3}, [%4];"
                 : "=r"(r0), "=r"(r1), "=r"(r2), "=r"(r3) : "r"(a));
}
__device__ __forceinline__ void mma16816(float* c, const uint32_t* a, const uint32_t* b) {
    asm volatile("mma.sync.aligned.m16n8k16.row.col.f32.bf16.bf16.f32 "
                 "{%0,%1,%2,%3}, {%4,%5,%6,%7}, {%8,%9}, {%0,%1,%2,%3};"
                 : "+f"(c[0]), "+f"(c[1]), "+f"(c[2]), "+f"(c[3])
                 : "r"(a[0]), "r"(a[1]), "r"(a[2]), "r"(a[3]), "r"(b[0]), "r"(b[1]));
}
__device__ __forceinline__ float sig_(float x) { return 1.0f / (1.0f + __expf(-x)); }

// ---- bf16-split HMMA GEMM: C = (Ah+Al)@Wh + Ah@Wl, fp32 accumulate --------
template<int BM, int BN_, int MT, int NT_, int EPI, bool SPLIT>
__global__ void __launch_bounds__(256, 2)
mma_gemm(const bf16* __restrict__ Ah, const bf16* __restrict__ Al,
         const bf16* __restrict__ Wh, const bf16* __restrict__ Wl,
         float* __restrict__ C, bf16* __restrict__ Shi, bf16* __restrict__ Slo,
         int N, int K, int a_cr, long long a_cs, int c_cr, long long c_cs,
         const float* __restrict__ aux0, const float* __restrict__ aux1,
         const float* __restrict__ aux2) {
    constexpr int WM = MT * 16, WN = NT_ * 8;
    constexpr int A_ROWB = BKT * 2 + 16;
    constexpr int B_ROWB = BN_ * 2 + 16;
    constexpr int A_TILE = BM * A_ROWB;
    constexpr int B_TILE = BKT * B_ROWB;
    constexpr int STAGE = 2 * A_TILE + 2 * B_TILE;
    constexpr int BCH = BN_ / 8;

    extern __shared__ char smem_raw[];
    const uint32_t sbase = (uint32_t)__cvta_generic_to_shared(smem_raw);

    const int tid = threadIdx.x;
    const int m0 = blockIdx.y * BM, n0 = blockIdx.x * BN_;
    const int warp = tid >> 5, lane = tid & 31;
    const int wid_m = warp >> 1, wid_n = warp & 1;
    const long long arow0 = (long long)(m0 / a_cr) * a_cs + (m0 % a_cr);

    float acc[MT][NT_][4];
#pragma unroll
    for (int i = 0; i < MT; ++i)
#pragma unroll
        for (int j = 0; j < NT_; ++j)
#pragma unroll
            for (int e = 0; e < 4; ++e) acc[i][j][e] = 0.0f;

    const int NKI = K / BKT;

    auto ldst = [&](int ks, int st) {
        const int k0 = ks * BKT;
        const uint32_t sb = sbase + st * STAGE;
#pragma unroll
        for (int t = 0; t < (BM * 4) / 256; ++t) {
            const int c = tid + t * 256;
            const int r = c >> 2, kc = (c & 3) * 8;
            const uint32_t off = r * A_ROWB + kc * 2;
            const long long gi = (arow0 + r) * (long long)K + k0 + kc;
            cp16(sb + off, Ah + gi);
            cp16(sb + A_TILE + off, Al + gi);
        }
        for (int c = tid; c < 4 * BN_; c += 256) {
            const int r = c / BCH, nc = c % BCH;
            const uint32_t off = 2 * A_TILE + r * B_ROWB + nc * 16;
            const long long gi = (long long)(k0 + r) * N + n0 + nc * 8;
            cp16(sb + off, Wh + gi);
            cp16(sb + B_TILE + off, Wl + gi);
        }
        asm volatile("cp.async.commit_group;\n");
    };

    ldst(0, 0);
    ldst(1, 1);

    for (int ks = 0; ks < NKI; ++ks) {
        if (ks < NKI - 1) asm volatile("cp.async.wait_group 1;\n");
        else              asm volatile("cp.async.wait_group 0;\n");
        __syncthreads();
        const uint32_t sb = sbase + (ks & 1) * STAGE;

#pragma unroll
        for (int kk = 0; kk < BKT; kk += 16) {
            uint32_t ah[MT][4], al[MT][4], b[NT_][2];
            const int arow = wid_m * WM + (lane & 15);
            const int acol = kk + (lane >> 4) * 8;
#pragma unroll
            for (int i = 0; i < MT; ++i) {
                const uint32_t ad = sb + (arow + i * 16) * A_ROWB + acol * 2;
                ldsm4(ah[i][0], ah[i][1], ah[i][2], ah[i][3], ad);
                ldsm4(al[i][0], al[i][1], al[i][2], al[i][3], ad + A_TILE);
            }
            const int brow = kk + (lane & 15);
            const uint32_t bbase = sb + 2 * A_TILE + brow * B_ROWB;
#pragma unroll
            for (int j2 = 0; j2 < NT_ / 2; ++j2) {
                const int bcol = wid_n * WN + j2 * 16 + (lane >> 4) * 8;
                ldsm4t(b[2*j2][0], b[2*j2][1], b[2*j2+1][0], b[2*j2+1][1],
                       bbase + bcol * 2);
            }
#pragma unroll
            for (int i = 0; i < MT; ++i)
#pragma unroll
                for (int j = 0; j < NT_; ++j) {
                    mma16816(acc[i][j], ah[i], b[j]);
                    mma16816(acc[i][j], al[i], b[j]);
                }
#pragma unroll
            for (int j2 = 0; j2 < NT_ / 2; ++j2) {
                const int bcol = wid_n * WN + j2 * 16 + (lane >> 4) * 8;
                ldsm4t(b[2*j2][0], b[2*j2][1], b[2*j2+1][0], b[2*j2+1][1],
                       bbase + B_TILE + bcol * 2);
            }
#pragma unroll
            for (int i = 0; i < MT; ++i)
#pragma unroll
                for (int j = 0; j < NT_; ++j)
                    mma16816(acc[i][j], ah[i], b[j]);
        }
        __syncthreads();
        if (ks + 2 < NKI) ldst(ks + 2, ks & 1);
    }

    const int gid = lane >> 2, tig = lane & 3;
    const long long crow0 = (long long)(m0 / c_cr) * c_cs + (m0 % c_cr);

#pragma unroll
    for (int i = 0; i < MT; ++i) {
        const int r = wid_m * WM + i * 16 + gid;
#pragma unroll
        for (int j = 0; j < NT_; ++j) {
            const int col = n0 + wid_n * WN + j * 8 + 2 * tig;
#pragma unroll
            for (int half = 0; half < 2; ++half) {
                const int rr = r + half * 8;
                const long long ci = (crow0 + rr) * (long long)N + col;
                const long long li = (long long)(m0 + rr) * N + col;
                float2 v;
#pragma unroll
                for (int e = 0; e < 2; ++e) {
                    const float a = acc[i][j][2 * half + e];
                    float o;
                    if      (EPI == 0) o = a;
                    else if (EPI == 1) o = sig_(a + aux0[col + e]);
                    else if (EPI == 2) o = aux1[ci + e] + aux2[li + e] * a;
                    else { const float s = sig_(a + aux0[col + e]);
                           o = s * aux1[li + e] + (1.0f - s) * aux2[li + e]; }
                    (&v.x)[e] = o;
                }
                *reinterpret_cast<float2*>(C + ci) = v;
                if (SPLIT) {
                    const bf16 h0 = __float2bfloat16(v.x), h1 = __float2bfloat16(v.y);
                    *reinterpret_cast<__nv_bfloat162*>(Shi + li) = __nv_bfloat162(h0, h1);
                    *reinterpret_cast<__nv_bfloat162*>(Slo + li) = __nv_bfloat162(
                        __float2bfloat16(v.x - __bfloat162float(h0)),
                        __float2bfloat16(v.y - __bfloat162float(h1)));
                }
            }
        }
    }
}

// ---- flash attention: 16 queries/block, warp w owns queries 2w, 2w+1 -------
__global__ void __launch_bounds__(256)
attn16(const float* __restrict__ Q, const float* __restrict__ Kp,
       const float* __restrict__ V, bf16* __restrict__ Ohi, bf16* __restrict__ Olo,
       int Lq, int Lk, float scale) {
    __shared__ float Ks[16][HDIM], Vs[16][HDIM];
    const int h = blockIdx.y, b = blockIdx.z, q0 = blockIdx.x * 16;
    const int tid = threadIdx.x, w = tid >> 5, l = tid & 31;
    const int qa = q0 + 2 * w;

    float qA[10], qB[10];
    const float* Qb = Q + ((long long)(b * Lq + qa)) * DD + h * HDIM;
#pragma unroll
    for (int t = 0; t < 10; ++t) { qA[t] = Qb[l + 32 * t]; qB[t] = Qb[DD + l + 32 * t]; }

    float mrun = -1e30f, sA = 0.0f, sB = 0.0f, accA[10], accB[10];
#pragma unroll
    for (int t = 0; t < 10; ++t) { accA[t] = 0.0f; accB[t] = 0.0f; }

    for (int c = 0; c < Lk / 16; ++c) {
        const long long k0 = (long long)(b * Lk + c * 16) * DD + h * HDIM;
#pragma unroll
        for (int t = 0; t < 5; ++t) {
            const int idx = tid + t * 256;
            const int row = idx / 80, c4 = idx % 80;
            *reinterpret_cast<float4*>(&Ks[row][c4 * 4]) =
                *reinterpret_cast<const float4*>(Kp + k0 + (long long)row * DD + c4 * 4);
            *reinterpret_cast<float4*>(&Vs[row][c4 * 4]) =
                *reinterpret_cast<const float4*>(V + k0 + (long long)row * DD + c4 * 4);
        }
        __syncthreads();
        float scA[16], scB[16], cmax = -1e30f;
#pragma unroll
        for (int k = 0; k < 16; ++k) {
            float da = 0.0f, db = 0.0f;
#pragma unroll
            for (int t = 0; t < 10; ++t) {
                const float kv = Ks[k][l + 32 * t];
                da += qA[t] * kv; db += qB[t] * kv;
            }
#pragma unroll
            for (int o = 16; o > 0; o >>= 1) {
                da += __shfl_xor_sync(0xFFFFFFFF, da, o);
                db += __shfl_xor_sync(0xFFFFFFFF, db, o);
            }
            scA[k] = da * scale; scB[k] = db * scale;
            cmax = fmaxf(cmax, fmaxf(scA[k], scB[k]));
        }
        const float mn = fmaxf(mrun, cmax);
        const float cr = __expf(mrun - mn);
        sA *= cr; sB *= cr;
#pragma unroll
        for (int t = 0; t < 10; ++t) { accA[t] *= cr; accB[t] *= cr; }
        mrun = mn;
#pragma unroll
        for (int k = 0; k < 16; ++k) {
            const float pa = __expf(scA[k] - mn), pb = __expf(scB[k] - mn);
            sA += pa; sB += pb;
#pragma unroll
            for (int t = 0; t < 10; ++t) {
                const float vv = Vs[k][l + 32 * t];
                accA[t] += pa * vv; accB[t] += pb * vv;
            }
        }
        __syncthreads();
    }
    const float iA = 1.0f / sA, iB = 1.0f / sB;
    bf16* Oh = Ohi + ((long long)(b * Lq + qa)) * DD + h * HDIM;
    bf16* Ol = Olo + ((long long)(b * Lq + qa)) * DD + h * HDIM;
#pragma unroll
    for (int t = 0; t < 10; ++t) {
        const float va = accA[t] * iA, vb = accB[t] * iB;
        const bf16 ha = __float2bfloat16(va), hb = __float2bfloat16(vb);
        Oh[l + 32 * t] = ha;      Ol[l + 32 * t] = __float2bfloat16(va - __bfloat162float(ha));
        Oh[DD + l + 32 * t] = hb; Ol[DD + l + 32 * t] = __float2bfloat16(vb - __bfloat162float(hb));
    }
}

struct WSrc { const float* p[11]; };

__global__ void wsplit_all(WSrc ws, bf16* __restrict__ hi, bf16* __restrict__ lo) {
    const int mat = blockIdx.y;
    const long long o = (long long)mat * WMAT + (long long)blockIdx.x * 256 + threadIdx.x;
    const float v = ws.p[mat][(long long)blockIdx.x * 256 + threadIdx.x];
    const bf16 h = __float2bfloat16(v);
    hi[o] = h; lo[o] = __float2bfloat16(v - __bfloat162float(h));
}

__global__ void split_id(const float* __restrict__ x, bf16* __restrict__ hi,
                         bf16* __restrict__ lo) {
    const long long o = (long long)blockIdx.x * 256 + threadIdx.x;
    const float v = x[o];
    const bf16 h = __float2bfloat16(v);
    hi[o] = h; lo[o] = __float2bfloat16(v - __bfloat162float(h));
}

__global__ void concat_split(const float* __restrict__ mem, const float* __restrict__ nm,
                             bf16* __restrict__ hi, bf16* __restrict__ lo) {
    const long long idx = (long long)blockIdx.x * 256 + threadIdx.x;
    const long long r = idx / (2 * DD);
    const int c = (int)(idx % (2 * DD));
    const float v = (c < DD) ? mem[r * DD + c] : nm[r * DD + c - DD];
    const bf16 h = __float2bfloat16(v);
    hi[idx] = h; lo[idx] = __float2bfloat16(v - __bfloat162float(h));
}

// ---- side streams for fork/join concurrency (created pre-main) -------------
struct SideStreams {
    cudaStream_t s1, s2;
    cudaEvent_t e0, eWs, eQG, eKVr, eOr, eVW, eMem;
    bool ok;
    SideStreams() {
        ok = cudaStreamCreateWithFlags(&s1, cudaStreamNonBlocking) == cudaSuccess &&
             cudaStreamCreateWithFlags(&s2, cudaStreamNonBlocking) == cudaSuccess &&
             cudaEventCreateWithFlags(&e0,  cudaEventDisableTiming) == cudaSuccess &&
             cudaEventCreateWithFlags(&eWs, cudaEventDisableTiming) == cudaSuccess &&
             cudaEventCreateWithFlags(&eQG, cudaEventDisableTiming) == cudaSuccess &&
             cudaEventCreateWithFlags(&eKVr,cudaEventDisableTiming) == cudaSuccess &&
             cudaEventCreateWithFlags(&eOr, cudaEventDisableTiming) == cudaSuccess &&
             cudaEventCreateWithFlags(&eVW, cudaEventDisableTiming) == cudaSuccess &&
             cudaEventCreateWithFlags(&eMem,cudaEventDisableTiming) == cudaSuccess;
    }
};
static SideStreams SS;

extern "C" void kernel_launch(void* const* d_in, const int* in_sizes, int n_in,
                              void* d_out, int out_size) {
    const float* hid      = (const float*)d_in[0];
    const float* init_mem = (const float*)d_in[1];
    const float* wq_r = (const float*)d_in[2];
    const float* wk_r = (const float*)d_in[3];
    const float* wv_r = (const float*)d_in[4];
    const float* wo_r = (const float*)d_in[5];
    const float* wg_r = (const float*)d_in[6];
    const float* bg_r = (const float*)d_in[7];
    const float* wqueries = (const float*)d_in[8];
    const float* wq_w = (const float*)d_in[9];
    const float* wk_w = (const float*)d_in[10];
    const float* wv_w = (const float*)d_in[11];
    const float* wo_w = (const float*)d_in[12];
    const float* wg_w = (const float*)d_in[13];
    const float* bg_w = (const float*)d_in[14];
    float* out = (float*)d_out;

    float *qr, *gate, *kw, *vw, *kr, *vr, *qw, *nm, *memA, *memB;
    bf16 *whi, *wlo, *hidhi, *hidlo, *chi, *clo, *ahi, *alo, *awhi, *awlo;
    bf16 *cathi, *catlo, *mAhi, *mAlo, *mBhi, *mBlo, *imhi, *imlo, *wqhi, *wqlo;
    cudaGetSymbolAddress((void**)&qr, g_qr);     cudaGetSymbolAddress((void**)&gate, g_gate);
    cudaGetSymbolAddress((void**)&kw, g_kw);     cudaGetSymbolAddress((void**)&vw, g_vw);
    cudaGetSymbolAddress((void**)&kr, g_kr);     cudaGetSymbolAddress((void**)&vr, g_vr);
    cudaGetSymbolAddress((void**)&qw, g_qw);     cudaGetSymbolAddress((void**)&nm, g_nm);
    cudaGetSymbolAddress((void**)&memA, g_memA); cudaGetSymbolAddress((void**)&memB, g_memB);
    cudaGetSymbolAddress((void**)&whi, g_whi);   cudaGetSymbolAddress((void**)&wlo, g_wlo);
    cudaGetSymbolAddress((void**)&hidhi, g_hidhi); cudaGetSymbolAddress((void**)&hidlo, g_hidlo);
    cudaGetSymbolAddress((void**)&chi, g_chi);   cudaGetSymbolAddress((void**)&clo, g_clo);
    cudaGetSymbolAddress((void**)&ahi, g_ahi);   cudaGetSymbolAddress((void**)&alo, g_alo);
    cudaGetSymbolAddress((void**)&awhi, g_awhi); cudaGetSymbolAddress((void**)&awlo, g_awlo);
    cudaGetSymbolAddress((void**)&cathi, g_cathi); cudaGetSymbolAddress((void**)&catlo, g_catlo);
    cudaGetSymbolAddress((void**)&mAhi, g_mAhi); cudaGetSymbolAddress((void**)&mAlo, g_mAlo);
    cudaGetSymbolAddress((void**)&mBhi, g_mBhi); cudaGetSymbolAddress((void**)&mBlo, g_mBlo);
    cudaGetSymbolAddress((void**)&imhi, g_imhi); cudaGetSymbolAddress((void**)&imlo, g_imlo);
    cudaGetSymbolAddress((void**)&wqhi, g_wqhi); cudaGetSymbolAddress((void**)&wqlo, g_wqlo);

    constexpr int SMEM_BIG = 2 * (2 * 128 * 80 + 2 * 32 * 336);   // 83968
    constexpr int SMEM_SM  = 2 * (2 * 64  * 80 + 2 * 32 * 144);   // 38912
    cudaFuncSetAttribute(mma_gemm<128,160,2,10,0,false>, cudaFuncAttributeMaxDynamicSharedMemorySize, SMEM_BIG);
    cudaFuncSetAttribute(mma_gemm<128,160,2,10,1,false>, cudaFuncAttributeMaxDynamicSharedMemorySize, SMEM_BIG);
    cudaFuncSetAttribute(mma_gemm<128,160,2,10,2,true >, cudaFuncAttributeMaxDynamicSharedMemorySize, SMEM_BIG);
    cudaFuncSetAttribute(mma_gemm<64,64,1,4,0,false>,    cudaFuncAttributeMaxDynamicSharedMemorySize, SMEM_SM);
    cudaFuncSetAttribute(mma_gemm<64,64,1,4,0,true >,    cudaFuncAttributeMaxDynamicSharedMemorySize, SMEM_SM);
    cudaFuncSetAttribute(mma_gemm<64,64,1,4,3,true >,    cudaFuncAttributeMaxDynamicSharedMemorySize, SMEM_SM);

    const float scale = 0.05590169943749474f;
    const size_t memBytesF = (size_t)MMEM * DD * sizeof(float);
    dim3 gBig(DD / 160, MBIG / 128);   // 256 blocks
    dim3 gSm (DD / 64,  MSM / 64);     // 160 blocks
    dim3 gQw (DD / 64,  MMEM / 64);    // 80 blocks

    const bool ok = SS.ok;
    cudaStream_t t1 = ok ? SS.s1 : 0;
    cudaStream_t t2 = ok ? SS.s2 : 0;

    // ---- prologue ----
    if (ok) { cudaEventRecord(SS.e0, 0); cudaStreamWaitEvent(t1, SS.e0, 0);
              cudaStreamWaitEvent(t2, SS.e0, 0); }
    WSrc ws;
    ws.p[0] = wq_r; ws.p[1] = wk_r; ws.p[2] = wv_r; ws.p[3] = wo_r; ws.p[4] = wg_r;
    ws.p[5] = wq_w; ws.p[6] = wk_w; ws.p[7] = wv_w; ws.p[8] = wo_w;
    ws.p[9] = wg_w; ws.p[10] = wg_w + (long long)WMAT;
    wsplit_all<<<dim3(WMAT/256, 11), 256, 0, 0>>>(ws, whi, wlo);
    if (ok) cudaEventRecord(SS.eWs, 0);

    split_id<<<(BATCH*STOT*DD)/256, 256, 0, t1>>>(hid, hidhi, hidlo);
    split_id<<<(MMEM*DD)/256, 256, 0, t2>>>(init_mem, imhi, imlo);
    split_id<<<(MMEM*DD)/256, 256, 0, t2>>>(wqueries, wqhi, wqlo);

    if (ok) { cudaStreamWaitEvent(t1, SS.eWs, 0); cudaStreamWaitEvent(t2, SS.eWs, 0); }
    // t2: qw chain + kr/vr(0)
    mma_gemm<64,64,1,4,0,false><<<gQw, 256, SMEM_SM, t2>>>(wqhi, wqlo,
        whi+OW_QW, wlo+OW_QW, qw, nullptr, nullptr, DD, DD, MMEM, 0, MMEM, 0,
        nullptr, nullptr, nullptr);
    cudaMemcpyAsync(qw + (size_t)MMEM*DD, qw, memBytesF, cudaMemcpyDeviceToDevice, t2);
    mma_gemm<64,64,1,4,0,false><<<gSm, 256, SMEM_SM, t2>>>(imhi, imlo,
        whi+OW_KR, wlo+OW_KR, kr, nullptr, nullptr, DD, DD, MMEM, 0, MSM, 0,
        nullptr, nullptr, nullptr);
    mma_gemm<64,64,1,4,0,false><<<gSm, 256, SMEM_SM, t2>>>(imhi, imlo,
        whi+OW_VR, wlo+OW_VR, vr, nullptr, nullptr, DD, DD, MMEM, 0, MSM, 0,
        nullptr, nullptr, nullptr);
    if (ok) cudaEventRecord(SS.eKVr, t2);
    // t1: qr(0)/gate(0)
    mma_gemm<128,160,2,10,0,false><<<gBig, 256, SMEM_BIG, t1>>>(hidhi, hidlo,
        whi+OW_QR, wlo+OW_QR, qr, nullptr, nullptr, DD, DD,
        SEGL, (long long)STOT, MBIG, 0, nullptr, nullptr, nullptr);
    mma_gemm<128,160,2,10,1,false><<<gBig, 256, SMEM_BIG, t1>>>(hidhi, hidlo,
        whi+OW_GR, wlo+OW_GR, gate, nullptr, nullptr, DD, DD,
        SEGL, (long long)STOT, MBIG, 0, bg_r, nullptr, nullptr);
    if (ok) cudaEventRecord(SS.eQG, t1);

    float* memf[2] = {memA, memB};
    bf16*  memh[2] = {mAhi, mBhi};
    bf16*  meml[2] = {mAlo, mBlo};
    int cur = 0;

    for (int i = 0; i < NSEG; ++i) {
        const float* segp = hid + (long long)i * SEGL * DD;
        float* outp = out + (long long)i * SEGL * DD;
        const bf16* nshi = hidhi + (long long)(i+1) * SEGL * DD;
        const bf16* nslo = hidlo + (long long)(i+1) * SEGL * DD;
        const bool NS = (i + 1 < NSEG);

        // attn_r(i): needs qr/gate(i) [eQG] and kr/vr(i) [eKVr]
        if (ok) { cudaStreamWaitEvent(0, SS.eQG, 0); cudaStreamWaitEvent(0, SS.eKVr, 0); }
        attn16<<<dim3(SEGL/16, NH, BATCH), 256, 0, 0>>>(qr, kr, vr, chi, clo,
                                                        SEGL, MMEM, scale);
        // or(i)
        mma_gemm<128,160,2,10,2,true><<<gBig, 256, SMEM_BIG, 0>>>(chi, clo,
            whi+OW_OR, wlo+OW_OR, outp, ahi, alo, DD, DD,
            MBIG, 0, SEGL, (long long)STOT, nullptr, segp, gate);
        if (ok) cudaEventRecord(SS.eOr, 0);

        // hoist next segment's qr/gate onto t2 (deps: or(i) freed the buffers)
        if (NS) {
            if (ok) cudaStreamWaitEvent(t2, SS.eOr, 0);
            mma_gemm<128,160,2,10,0,false><<<gBig, 256, SMEM_BIG, t2>>>(nshi, nslo,
                whi+OW_QR, wlo+OW_QR, qr, nullptr, nullptr, DD, DD,
                SEGL, (long long)STOT, MBIG, 0, nullptr, nullptr, nullptr);
            mma_gemm<128,160,2,10,1,false><<<gBig, 256, SMEM_BIG, t2>>>(nshi, nslo,
                whi+OW_GR, wlo+OW_GR, gate, nullptr, nullptr, DD, DD,
                SEGL, (long long)STOT, MBIG, 0, bg_r, nullptr, nullptr);
            if (ok) cudaEventRecord(SS.eQG, t2);
        }

        // kw(i) on main, vw(i) on t1
        mma_gemm<128,160,2,10,0,false><<<gBig, 256, SMEM_BIG, 0>>>(ahi, alo,
            whi+OW_KW, wlo+OW_KW, kw, nullptr, nullptr, DD, DD,
            MBIG, 0, MBIG, 0, nullptr, nullptr, nullptr);
        if (ok) cudaStreamWaitEvent(t1, SS.eOr, 0);
        mma_gemm<128,160,2,10,0,false><<<gBig, 256, SMEM_BIG, t1>>>(ahi, alo,
            whi+OW_VW, wlo+OW_VW, vw, nullptr, nullptr, DD, DD,
            MBIG, 0, MBIG, 0, nullptr, nullptr, nullptr);
        if (ok) { cudaEventRecord(SS.eVW, t1); cudaStreamWaitEvent(0, SS.eVW, 0); }

        attn16<<<dim3(MMEM/16, NH, BATCH), 256, 0, 0>>>(qw, kw, vw, awhi, awlo,
                                                        MMEM, SEGL, scale);

        if (i == 0) {
            mma_gemm<64,64,1,4,0,true><<<gSm, 256, SMEM_SM, 0>>>(awhi, awlo,
                whi+OW_OW, wlo+OW_OW, memf[0], mAhi, mAlo, DD, DD,
                MSM, 0, MSM, 0, nullptr, nullptr, nullptr);
            cur = 0;
        } else {
            mma_gemm<64,64,1,4,0,false><<<gSm, 256, SMEM_SM, 0>>>(awhi, awlo,
                whi+OW_OW, wlo+OW_OW, nm, nullptr, nullptr, DD, DD,
                MSM, 0, MSM, 0, nullptr, nullptr, nullptr);
            const int nxt = cur ^ 1;
            concat_split<<<(MSM*2*DD)/256, 256, 0, 0>>>(memf[cur], nm, cathi, catlo);
            mma_gemm<64,64,1,4,3,true><<<gSm, 256, SMEM_SM, 0>>>(cathi, catlo,
                whi+OW_GW, wlo+OW_GW, memf[nxt], memh[nxt], meml[nxt], DD, 2*DD,
                MSM, 0, MSM, 0, bg_w, nm, memf[cur]);
            cur = nxt;
        }
        if (ok) cudaEventRecord(SS.eMem, 0);

        // kr/vr(i+1) on t1 (dep: new memory)
        if (NS) {
            if (ok) cudaStreamWaitEvent(t1, SS.eMem, 0);
            mma_gemm<64,64,1,4,0,false><<<gSm, 256, SMEM_SM, t1>>>(memh[cur], meml[cur],
                whi+OW_KR, wlo+OW_KR, kr, nullptr, nullptr, DD, DD,
                MSM, 0, MSM, 0, nullptr, nullptr, nullptr);
            mma_gemm<64,64,1,4,0,false><<<gSm, 256, SMEM_SM, t1>>>(memh[cur], meml[cur],
                whi+OW_VR, wlo+OW_VR, vr, nullptr, nullptr, DD, DD,
                MSM, 0, MSM, 0, nullptr, nullptr, nullptr);
            if (ok) cudaEventRecord(SS.eKVr, t1);
        }
    }
}

// round 12
// speedup vs baseline: 1.3607x; 1.2104x over previous
#include <cuda_runtime.h>
#include <cuda_fp16.h>
#include <math.h>
#include <stdint.h>
typedef __half h16;

#define DD    2560
#define HDIM  320
#define NH    8
#define SEGL  1024
#define STOT  4096
#define BATCH 2
#define MMEM  128
#define NSEG  4
#define MBIG  (BATCH*SEGL)
#define MSM   (BATCH*MMEM)
#define BKT   32

// fp32 scratch
__device__ float g_qr[MBIG*DD], g_gate[MBIG*DD], g_kw[MBIG*DD], g_vw[MBIG*DD];
__device__ float g_kr[MSM*DD], g_vr[MSM*DD], g_qw[MSM*DD], g_nm[MSM*DD];
__device__ float g_memA[MSM*DD], g_memB[MSM*DD];
// fp16 scratch
#define WMAT (DD*DD)
__device__ __align__(16) h16 g_whi[11LL*WMAT];
__device__ __align__(16) h16 g_hidhi[BATCH*STOT*DD], g_hidlo[BATCH*STOT*DD];
__device__ __align__(16) h16 g_chi[MBIG*DD], g_clo[MBIG*DD];
__device__ __align__(16) h16 g_ahi[MBIG*DD], g_alo[MBIG*DD];
__device__ __align__(16) h16 g_awhi[MSM*DD], g_awlo[MSM*DD];
__device__ __align__(16) h16 g_cathi[MSM*2*DD], g_catlo[MSM*2*DD];
__device__ __align__(16) h16 g_mAhi[MSM*DD], g_mAlo[MSM*DD];
__device__ __align__(16) h16 g_mBhi[MSM*DD], g_mBlo[MSM*DD];
__device__ __align__(16) h16 g_imhi[MMEM*DD], g_imlo[MMEM*DD];
__device__ __align__(16) h16 g_wqhi[MMEM*DD], g_wqlo[MMEM*DD];

#define OW_QR (0LL*WMAT)
#define OW_KR (1LL*WMAT)
#define OW_VR (2LL*WMAT)
#define OW_OR (3LL*WMAT)
#define OW_GR (4LL*WMAT)
#define OW_QW (5LL*WMAT)
#define OW_KW (6LL*WMAT)
#define OW_VW (7LL*WMAT)
#define OW_OW (8LL*WMAT)
#define OW_GW (9LL*WMAT)

__device__ __forceinline__ void cp16(uint32_t s, const void* g) {
    asm volatile("cp.async.cg.shared.global [%0], [%1], 16;\n" :: "r"(s), "l"(g));
}
__device__ __forceinline__ void ldsm4(uint32_t& r0, uint32_t& r1, uint32_t& r2,
                                      uint32_t& r3, uint32_t a) {
    asm volatile("ldmatrix.sync.aligned.m8n8.x4.shared.b16 {%0,%1,%2,%3}, [%4];"
                 : "=r"(r0), "=r"(r1), "=r"(r2), "=r"(r3) : "r"(a));
}
__device__ __forceinline__ void ldsm4t(uint32_t& r0, uint32_t& r1, uint32_t& r2,
                                       uint32_t& r3, uint32_t a) {
    asm volatile("ldmatrix.sync.aligned.m8n8.x4.trans.shared.b16 {%0,%1,%2,%3}, [%4];"
                 : "=r"(r0), "=r"(r1), "=r"(r2), "=r"(r3) : "r"(a));
}
__device__ __forceinline__ void mma16816(float* c, const uint32_t* a, const uint32_t* b) {
    asm volatile("mma.sync.aligned.m16n8k16.row.col.f32.f16.f16.f32 "
                 "{%0,%1,%2,%3}, {%4,%5,%6,%7}, {%8,%9}, {%0,%1,%2,%3};"
                 : "+f"(c[0]), "+f"(c[1]), "+f"(c[2]), "+f"(c[3])
                 : "r"(a[0]), "r"(a[1]), "r"(a[2]), "r"(a[3]), "r"(b[0]), "r"(b[1]));
}
__device__ __forceinline__ float sig_(float x) { return 1.0f / (1.0f + __expf(-x)); }
__device__ __forceinline__ void split1(float v, h16& hi, h16& lo) {
    hi = __float2half_rn(v);
    lo = __float2half_rn(v - __half2float(hi));
}

// ---- fp16 2-pass HMMA GEMM: C = (Ah+Al)@Wh, fp32 accumulate ---------------
// Block tile BM x BN_. 8 warps as 4 rows x 2 cols. WM=MT*16, WN=NT_*8.
template<int BM, int BN_, int MT, int NT_, int EPI, bool SPLIT>
__global__ void __launch_bounds__(256, 2)
mma_gemm(const h16* __restrict__ Ah, const h16* __restrict__ Al,
         const h16* __restrict__ Wh,
         float* __restrict__ C, h16* __restrict__ Shi, h16* __restrict__ Slo,
         int N, int K, int a_cr, long long a_cs, int c_cr, long long c_cs,
         const float* __restrict__ aux0, const float* __restrict__ aux1,
         const float* __restrict__ aux2) {
    constexpr int WM = MT * 16, WN = NT_ * 8;
    constexpr int A_ROWB = BKT * 2 + 16;
    constexpr int B_ROWB = BN_ * 2 + 16;
    constexpr int A_TILE = BM * A_ROWB;
    constexpr int B_TILE = BKT * B_ROWB;
    constexpr int STAGE = 2 * A_TILE + B_TILE;
    constexpr int BCH = BN_ / 8;

    extern __shared__ char smem_raw[];
    const uint32_t sbase = (uint32_t)__cvta_generic_to_shared(smem_raw);

    const int tid = threadIdx.x;
    const int m0 = blockIdx.y * BM, n0 = blockIdx.x * BN_;
    const int warp = tid >> 5, lane = tid & 31;
    const int wid_m = warp >> 1, wid_n = warp & 1;
    const long long arow0 = (long long)(m0 / a_cr) * a_cs + (m0 % a_cr);

    float acc[MT][NT_][4];
#pragma unroll
    for (int i = 0; i < MT; ++i)
#pragma unroll
        for (int j = 0; j < NT_; ++j)
#pragma unroll
            for (int e = 0; e < 4; ++e) acc[i][j][e] = 0.0f;

    const int NKI = K / BKT;

    auto ldst = [&](int ks, int st) {
        const int k0 = ks * BKT;
        const uint32_t sb = sbase + st * STAGE;
#pragma unroll
        for (int t = 0; t < (BM * 4) / 256; ++t) {
            const int c = tid + t * 256;
            const int r = c >> 2, kc = (c & 3) * 8;
            const uint32_t off = r * A_ROWB + kc * 2;
            const long long gi = (arow0 + r) * (long long)K + k0 + kc;
            cp16(sb + off, Ah + gi);
            cp16(sb + A_TILE + off, Al + gi);
        }
        for (int c = tid; c < 4 * BN_; c += 256) {
            const int r = c / BCH, nc = c % BCH;
            const uint32_t off = 2 * A_TILE + r * B_ROWB + nc * 16;
            const long long gi = (long long)(k0 + r) * N + n0 + nc * 8;
            cp16(sb + off, Wh + gi);
        }
        asm volatile("cp.async.commit_group;\n");
    };

    ldst(0, 0);
    ldst(1, 1);

    for (int ks = 0; ks < NKI; ++ks) {
        if (ks < NKI - 1) asm volatile("cp.async.wait_group 1;\n");
        else              asm volatile("cp.async.wait_group 0;\n");
        __syncthreads();
        const uint32_t sb = sbase + (ks & 1) * STAGE;

#pragma unroll
        for (int kk = 0; kk < BKT; kk += 16) {
            uint32_t ah[MT][4], al[MT][4], b[NT_][2];
            const int arow = wid_m * WM + (lane & 15);
            const int acol = kk + (lane >> 4) * 8;
#pragma unroll
            for (int i = 0; i < MT; ++i) {
                const uint32_t ad = sb + (arow + i * 16) * A_ROWB + acol * 2;
                ldsm4(ah[i][0], ah[i][1], ah[i][2], ah[i][3], ad);
                ldsm4(al[i][0], al[i][1], al[i][2], al[i][3], ad + A_TILE);
            }
            const int brow = kk + (lane & 15);
            const uint32_t bbase = sb + 2 * A_TILE + brow * B_ROWB;
#pragma unroll
            for (int j2 = 0; j2 < NT_ / 2; ++j2) {
                const int bcol = wid_n * WN + j2 * 16 + (lane >> 4) * 8;
                ldsm4t(b[2*j2][0], b[2*j2][1], b[2*j2+1][0], b[2*j2+1][1],
                       bbase + bcol * 2);
            }
#pragma unroll
            for (int i = 0; i < MT; ++i)
#pragma unroll
                for (int j = 0; j < NT_; ++j) {
                    mma16816(acc[i][j], ah[i], b[j]);
                    mma16816(acc[i][j], al[i], b[j]);
                }
        }
        __syncthreads();
        if (ks + 2 < NKI) ldst(ks + 2, ks & 1);
    }

    const int gid = lane >> 2, tig = lane & 3;
    const long long crow0 = (long long)(m0 / c_cr) * c_cs + (m0 % c_cr);

#pragma unroll
    for (int i = 0; i < MT; ++i) {
        const int r = wid_m * WM + i * 16 + gid;
#pragma unroll
        for (int j = 0; j < NT_; ++j) {
            const int col = n0 + wid_n * WN + j * 8 + 2 * tig;
#pragma unroll
            for (int half = 0; half < 2; ++half) {
                const int rr = r + half * 8;
                const long long ci = (crow0 + rr) * (long long)N + col;
                const long long li = (long long)(m0 + rr) * N + col;
                float2 v;
#pragma unroll
                for (int e = 0; e < 2; ++e) {
                    const float a = acc[i][j][2 * half + e];
                    float o;
                    if      (EPI == 0) o = a;
                    else if (EPI == 1) o = sig_(a + aux0[col + e]);
                    else if (EPI == 2) o = aux1[ci + e] + aux2[li + e] * a;
                    else { const float s = sig_(a + aux0[col + e]);
                           o = s * aux1[li + e] + (1.0f - s) * aux2[li + e]; }
                    (&v.x)[e] = o;
                }
                *reinterpret_cast<float2*>(C + ci) = v;
                if (SPLIT) {
                    h16 h0, l0, h1, l1;
                    split1(v.x, h0, l0);
                    split1(v.y, h1, l1);
                    *reinterpret_cast<__half2*>(Shi + li) = __half2(h0, h1);
                    *reinterpret_cast<__half2*>(Slo + li) = __half2(l0, l1);
                }
            }
        }
    }
}

// ---- flash attention: 16 queries/block, warp w owns queries 2w, 2w+1 -------
__global__ void __launch_bounds__(256)
attn16(const float* __restrict__ Q, const float* __restrict__ Kp,
       const float* __restrict__ V, h16* __restrict__ Ohi, h16* __restrict__ Olo,
       int Lq, int Lk, float scale) {
    __shared__ float Ks[16][HDIM], Vs[16][HDIM];
    const int h = blockIdx.y, b = blockIdx.z, q0 = blockIdx.x * 16;
    const int tid = threadIdx.x, w = tid >> 5, l = tid & 31;
    const int qa = q0 + 2 * w;

    float qA[10], qB[10];
    const float* Qb = Q + ((long long)(b * Lq + qa)) * DD + h * HDIM;
#pragma unroll
    for (int t = 0; t < 10; ++t) { qA[t] = Qb[l + 32 * t]; qB[t] = Qb[DD + l + 32 * t]; }

    float mrun = -1e30f, sA = 0.0f, sB = 0.0f, accA[10], accB[10];
#pragma unroll
    for (int t = 0; t < 10; ++t) { accA[t] = 0.0f; accB[t] = 0.0f; }

    for (int c = 0; c < Lk / 16; ++c) {
        const long long k0 = (long long)(b * Lk + c * 16) * DD + h * HDIM;
#pragma unroll
        for (int t = 0; t < 5; ++t) {
            const int idx = tid + t * 256;
            const int row = idx / 80, c4 = idx % 80;
            *reinterpret_cast<float4*>(&Ks[row][c4 * 4]) =
                *reinterpret_cast<const float4*>(Kp + k0 + (long long)row * DD + c4 * 4);
            *reinterpret_cast<float4*>(&Vs[row][c4 * 4]) =
                *reinterpret_cast<const float4*>(V + k0 + (long long)row * DD + c4 * 4);
        }
        __syncthreads();
        float scA[16], scB[16], cmax = -1e30f;
#pragma unroll
        for (int k = 0; k < 16; ++k) {
            float da = 0.0f, db = 0.0f;
#pragma unroll
            for (int t = 0; t < 10; ++t) {
                const float kv = Ks[k][l + 32 * t];
                da += qA[t] * kv; db += qB[t] * kv;
            }
#pragma unroll
            for (int o = 16; o > 0; o >>= 1) {
                da += __shfl_xor_sync(0xFFFFFFFF, da, o);
                db += __shfl_xor_sync(0xFFFFFFFF, db, o);
            }
            scA[k] = da * scale; scB[k] = db * scale;
            cmax = fmaxf(cmax, fmaxf(scA[k], scB[k]));
        }
        const float mn = fmaxf(mrun, cmax);
        const float cr = __expf(mrun - mn);
        sA *= cr; sB *= cr;
#pragma unroll
        for (int t = 0; t < 10; ++t) { accA[t] *= cr; accB[t] *= cr; }
        mrun = mn;
#pragma unroll
        for (int k = 0; k < 16; ++k) {
            const float pa = __expf(scA[k] - mn), pb = __expf(scB[k] - mn);
            sA += pa; sB += pb;
#pragma unroll
            for (int t = 0; t < 10; ++t) {
                const float vv = Vs[k][l + 32 * t];
                accA[t] += pa * vv; accB[t] += pb * vv;
            }
        }
        __syncthreads();
    }
    const float iA = 1.0f / sA, iB = 1.0f / sB;
    h16* Oh = Ohi + ((long long)(b * Lq + qa)) * DD + h * HDIM;
    h16* Ol = Olo + ((long long)(b * Lq + qa)) * DD + h * HDIM;
#pragma unroll
    for (int t = 0; t < 10; ++t) {
        h16 ha, la, hb, lb;
        split1(accA[t] * iA, ha, la);
        split1(accB[t] * iB, hb, lb);
        Oh[l + 32 * t] = ha;      Ol[l + 32 * t] = la;
        Oh[DD + l + 32 * t] = hb; Ol[DD + l + 32 * t] = lb;
    }
}

struct WSrc { const float* p[11]; };

__global__ void wsplit_all(WSrc ws, h16* __restrict__ hi) {
    const int mat = blockIdx.y;
    const long long o = (long long)mat * WMAT + (long long)blockIdx.x * 256 + threadIdx.x;
    hi[o] = __float2half_rn(ws.p[mat][(long long)blockIdx.x * 256 + threadIdx.x]);
}

__global__ void split_id(const float* __restrict__ x, h16* __restrict__ hi,
                         h16* __restrict__ lo) {
    const long long o = (long long)blockIdx.x * 256 + threadIdx.x;
    h16 h, l;
    split1(x[o], h, l);
    hi[o] = h; lo[o] = l;
}

__global__ void concat_split(const float* __restrict__ mem, const float* __restrict__ nm,
                             h16* __restrict__ hi, h16* __restrict__ lo) {
    const long long idx = (long long)blockIdx.x * 256 + threadIdx.x;
    const long long r = idx / (2 * DD);
    const int c = (int)(idx % (2 * DD));
    const float v = (c < DD) ? mem[r * DD + c] : nm[r * DD + c - DD];
    h16 h, l;
    split1(v, h, l);
    hi[idx] = h; lo[idx] = l;
}

// ---- side streams for fork/join concurrency (created pre-main) -------------
struct SideStreams {
    cudaStream_t s1, s2;
    cudaEvent_t e0, eWs, eQG, eKVr, eOr, eVW, eMem;
    bool ok;
    SideStreams() {
        ok = cudaStreamCreateWithFlags(&s1, cudaStreamNonBlocking) == cudaSuccess &&
             cudaStreamCreateWithFlags(&s2, cudaStreamNonBlocking) == cudaSuccess &&
             cudaEventCreateWithFlags(&e0,  cudaEventDisableTiming) == cudaSuccess &&
             cudaEventCreateWithFlags(&eWs, cudaEventDisableTiming) == cudaSuccess &&
             cudaEventCreateWithFlags(&eQG, cudaEventDisableTiming) == cudaSuccess &&
             cudaEventCreateWithFlags(&eKVr,cudaEventDisableTiming) == cudaSuccess &&
             cudaEventCreateWithFlags(&eOr, cudaEventDisableTiming) == cudaSuccess &&
             cudaEventCreateWithFlags(&eVW, cudaEventDisableTiming) == cudaSuccess &&
             cudaEventCreateWithFlags(&eMem,cudaEventDisableTiming) == cudaSuccess;
    }
};
static SideStreams SS;

extern "C" void kernel_launch(void* const* d_in, const int* in_sizes, int n_in,
                              void* d_out, int out_size) {
    const float* hid      = (const float*)d_in[0];
    const float* init_mem = (const float*)d_in[1];
    const float* wq_r = (const float*)d_in[2];
    const float* wk_r = (const float*)d_in[3];
    const float* wv_r = (const float*)d_in[4];
    const float* wo_r = (const float*)d_in[5];
    const float* wg_r = (const float*)d_in[6];
    const float* bg_r = (const float*)d_in[7];
    const float* wqueries = (const float*)d_in[8];
    const float* wq_w = (const float*)d_in[9];
    const float* wk_w = (const float*)d_in[10];
    const float* wv_w = (const float*)d_in[11];
    const float* wo_w = (const float*)d_in[12];
    const float* wg_w = (const float*)d_in[13];
    const float* bg_w = (const float*)d_in[14];
    float* out = (float*)d_out;

    float *qr, *gate, *kw, *vw, *kr, *vr, *qw, *nm, *memA, *memB;
    h16 *whi, *hidhi, *hidlo, *chi, *clo, *ahi, *alo, *awhi, *awlo;
    h16 *cathi, *catlo, *mAhi, *mAlo, *mBhi, *mBlo, *imhi, *imlo, *wqhi, *wqlo;
    cudaGetSymbolAddress((void**)&qr, g_qr);     cudaGetSymbolAddress((void**)&gate, g_gate);
    cudaGetSymbolAddress((void**)&kw, g_kw);     cudaGetSymbolAddress((void**)&vw, g_vw);
    cudaGetSymbolAddress((void**)&kr, g_kr);     cudaGetSymbolAddress((void**)&vr, g_vr);
    cudaGetSymbolAddress((void**)&qw, g_qw);     cudaGetSymbolAddress((void**)&nm, g_nm);
    cudaGetSymbolAddress((void**)&memA, g_memA); cudaGetSymbolAddress((void**)&memB, g_memB);
    cudaGetSymbolAddress((void**)&whi, g_whi);
    cudaGetSymbolAddress((void**)&hidhi, g_hidhi); cudaGetSymbolAddress((void**)&hidlo, g_hidlo);
    cudaGetSymbolAddress((void**)&chi, g_chi);   cudaGetSymbolAddress((void**)&clo, g_clo);
    cudaGetSymbolAddress((void**)&ahi, g_ahi);   cudaGetSymbolAddress((void**)&alo, g_alo);
    cudaGetSymbolAddress((void**)&awhi, g_awhi); cudaGetSymbolAddress((void**)&awlo, g_awlo);
    cudaGetSymbolAddress((void**)&cathi, g_cathi); cudaGetSymbolAddress((void**)&catlo, g_catlo);
    cudaGetSymbolAddress((void**)&mAhi, g_mAhi); cudaGetSymbolAddress((void**)&mAlo, g_mAlo);
    cudaGetSymbolAddress((void**)&mBhi, g_mBhi); cudaGetSymbolAddress((void**)&mBlo, g_mBlo);
    cudaGetSymbolAddress((void**)&imhi, g_imhi); cudaGetSymbolAddress((void**)&imlo, g_imlo);
    cudaGetSymbolAddress((void**)&wqhi, g_wqhi); cudaGetSymbolAddress((void**)&wqlo, g_wqlo);

    constexpr int SMEM_BIG = 2 * (2 * 128 * 80 + 32 * 336);   // 62464
    constexpr int SMEM_SM  = 2 * (2 * 64  * 80 + 32 * 144);   // 29696
    cudaFuncSetAttribute(mma_gemm<128,160,2,10,0,false>, cudaFuncAttributeMaxDynamicSharedMemorySize, SMEM_BIG);
    cudaFuncSetAttribute(mma_gemm<128,160,2,10,1,false>, cudaFuncAttributeMaxDynamicSharedMemorySize, SMEM_BIG);
    cudaFuncSetAttribute(mma_gemm<128,160,2,10,2,true >, cudaFuncAttributeMaxDynamicSharedMemorySize, SMEM_BIG);
    cudaFuncSetAttribute(mma_gemm<64,64,1,4,0,false>,    cudaFuncAttributeMaxDynamicSharedMemorySize, SMEM_SM);
    cudaFuncSetAttribute(mma_gemm<64,64,1,4,0,true >,    cudaFuncAttributeMaxDynamicSharedMemorySize, SMEM_SM);
    cudaFuncSetAttribute(mma_gemm<64,64,1,4,3,true >,    cudaFuncAttributeMaxDynamicSharedMemorySize, SMEM_SM);

    const float scale = 0.05590169943749474f;
    const size_t memBytesF = (size_t)MMEM * DD * sizeof(float);
    dim3 gBig(DD / 160, MBIG / 128);   // 256 blocks
    dim3 gSm (DD / 64,  MSM / 64);     // 160 blocks
    dim3 gQw (DD / 64,  MMEM / 64);    // 80 blocks

    const bool ok = SS.ok;
    cudaStream_t t1 = ok ? SS.s1 : 0;
    cudaStream_t t2 = ok ? SS.s2 : 0;

    // ---- prologue ----
    if (ok) { cudaEventRecord(SS.e0, 0); cudaStreamWaitEvent(t1, SS.e0, 0);
              cudaStreamWaitEvent(t2, SS.e0, 0); }
    WSrc ws;
    ws.p[0] = wq_r; ws.p[1] = wk_r; ws.p[2] = wv_r; ws.p[3] = wo_r; ws.p[4] = wg_r;
    ws.p[5] = wq_w; ws.p[6] = wk_w; ws.p[7] = wv_w; ws.p[8] = wo_w;
    ws.p[9] = wg_w; ws.p[10] = wg_w + (long long)WMAT;
    wsplit_all<<<dim3(WMAT/256, 11), 256, 0, 0>>>(ws, whi);
    if (ok) cudaEventRecord(SS.eWs, 0);

    split_id<<<(BATCH*STOT*DD)/256, 256, 0, t1>>>(hid, hidhi, hidlo);
    split_id<<<(MMEM*DD)/256, 256, 0, t2>>>(init_mem, imhi, imlo);
    split_id<<<(MMEM*DD)/256, 256, 0, t2>>>(wqueries, wqhi, wqlo);

    if (ok) { cudaStreamWaitEvent(t1, SS.eWs, 0); cudaStreamWaitEvent(t2, SS.eWs, 0); }
    // t2: qw chain + kr/vr(0)
    mma_gemm<64,64,1,4,0,false><<<gQw, 256, SMEM_SM, t2>>>(wqhi, wqlo,
        whi+OW_QW, qw, nullptr, nullptr, DD, DD, MMEM, 0, MMEM, 0,
        nullptr, nullptr, nullptr);
    cudaMemcpyAsync(qw + (size_t)MMEM*DD, qw, memBytesF, cudaMemcpyDeviceToDevice, t2);
    mma_gemm<64,64,1,4,0,false><<<gSm, 256, SMEM_SM, t2>>>(imhi, imlo,
        whi+OW_KR, kr, nullptr, nullptr, DD, DD, MMEM, 0, MSM, 0,
        nullptr, nullptr, nullptr);
    mma_gemm<64,64,1,4,0,false><<<gSm, 256, SMEM_SM, t2>>>(imhi, imlo,
        whi+OW_VR, vr, nullptr, nullptr, DD, DD, MMEM, 0, MSM, 0,
        nullptr, nullptr, nullptr);
    if (ok) cudaEventRecord(SS.eKVr, t2);
    // t1: qr(0)/gate(0)
    mma_gemm<128,160,2,10,0,false><<<gBig, 256, SMEM_BIG, t1>>>(hidhi, hidlo,
        whi+OW_QR, qr, nullptr, nullptr, DD, DD,
        SEGL, (long long)STOT, MBIG, 0, nullptr, nullptr, nullptr);
    mma_gemm<128,160,2,10,1,false><<<gBig, 256, SMEM_BIG, t1>>>(hidhi, hidlo,
        whi+OW_GR, gate, nullptr, nullptr, DD, DD,
        SEGL, (long long)STOT, MBIG, 0, bg_r, nullptr, nullptr);
    if (ok) cudaEventRecord(SS.eQG, t1);

    float* memf[2] = {memA, memB};
    h16*   memh[2] = {mAhi, mBhi};
    h16*   meml[2] = {mAlo, mBlo};
    int cur = 0;

    for (int i = 0; i < NSEG; ++i) {
        const float* segp = hid + (long long)i * SEGL * DD;
        float* outp = out + (long long)i * SEGL * DD;
        const h16* nshi = hidhi + (long long)(i+1) * SEGL * DD;
        const h16* nslo = hidlo + (long long)(i+1) * SEGL * DD;
        const bool NS = (i + 1 < NSEG);

        if (ok) { cudaStreamWaitEvent(0, SS.eQG, 0); cudaStreamWaitEvent(0, SS.eKVr, 0); }
        attn16<<<dim3(SEGL/16, NH, BATCH), 256, 0, 0>>>(qr, kr, vr, chi, clo,
                                                        SEGL, MMEM, scale);
        mma_gemm<128,160,2,10,2,true><<<gBig, 256, SMEM_BIG, 0>>>(chi, clo,
            whi+OW_OR, outp, ahi, alo, DD, DD,
            MBIG, 0, SEGL, (long long)STOT, nullptr, segp, gate);
        if (ok) cudaEventRecord(SS.eOr, 0);

        if (NS) {
            if (ok) cudaStreamWaitEvent(t2, SS.eOr, 0);
            mma_gemm<128,160,2,10,0,false><<<gBig, 256, SMEM_BIG, t2>>>(nshi, nslo,
                whi+OW_QR, qr, nullptr, nullptr, DD, DD,
                SEGL, (long long)STOT, MBIG, 0, nullptr, nullptr, nullptr);
            mma_gemm<128,160,2,10,1,false><<<gBig, 256, SMEM_BIG, t2>>>(nshi, nslo,
                whi+OW_GR, gate, nullptr, nullptr, DD, DD,
                SEGL, (long long)STOT, MBIG, 0, bg_r, nullptr, nullptr);
            if (ok) cudaEventRecord(SS.eQG, t2);
        }

        mma_gemm<128,160,2,10,0,false><<<gBig, 256, SMEM_BIG, 0>>>(ahi, alo,
            whi+OW_KW, kw, nullptr, nullptr, DD, DD,
            MBIG, 0, MBIG, 0, nullptr, nullptr, nullptr);
        if (ok) cudaStreamWaitEvent(t1, SS.eOr, 0);
        mma_gemm<128,160,2,10,0,false><<<gBig, 256, SMEM_BIG, t1>>>(ahi, alo,
            whi+OW_VW, vw, nullptr, nullptr, DD, DD,
            MBIG, 0, MBIG, 0, nullptr, nullptr, nullptr);
        if (ok) { cudaEventRecord(SS.eVW, t1); cudaStreamWaitEvent(0, SS.eVW, 0); }

        attn16<<<dim3(MMEM/16, NH, BATCH), 256, 0, 0>>>(qw, kw, vw, awhi, awlo,
                                                        MMEM, SEGL, scale);

        if (i == 0) {
            mma_gemm<64,64,1,4,0,true><<<gSm, 256, SMEM_SM, 0>>>(awhi, awlo,
                whi+OW_OW, memf[0], mAhi, mAlo, DD, DD,
                MSM, 0, MSM, 0, nullptr, nullptr, nullptr);
            cur = 0;
        } else {
            mma_gemm<64,64,1,4,0,false><<<gSm, 256, SMEM_SM, 0>>>(awhi, awlo,
                whi+OW_OW, nm, nullptr, nullptr, DD, DD,
                MSM, 0, MSM, 0, nullptr, nullptr, nullptr);
            const int nxt = cur ^ 1;
            concat_split<<<(MSM*2*DD)/256, 256, 0, 0>>>(memf[cur], nm, cathi, catlo);
            mma_gemm<64,64,1,4,3,true><<<gSm, 256, SMEM_SM, 0>>>(cathi, catlo,
                whi+OW_GW, memf[nxt], memh[nxt], meml[nxt], DD, 2*DD,
                MSM, 0, MSM, 0, bg_w, nm, memf[cur]);
            cur = nxt;
        }
        if (ok) cudaEventRecord(SS.eMem, 0);

        if (NS) {
            if (ok) cudaStreamWaitEvent(t1, SS.eMem, 0);
            mma_gemm<64,64,1,4,0,false><<<gSm, 256, SMEM_SM, t1>>>(memh[cur], meml[cur],
                whi+OW_KR, kr, nullptr, nullptr, DD, DD,
                MSM, 0, MSM, 0, nullptr, nullptr, nullptr);
            mma_gemm<64,64,1,4,0,false><<<gSm, 256, SMEM_SM, t1>>>(memh[cur], meml[cur],
                whi+OW_VR, vr, nullptr, nullptr, DD, DD,
                MSM, 0, MSM, 0, nullptr, nullptr, nullptr);
            if (ok) cudaEventRecord(SS.eKVr, t1);
        }
    }
}

// round 13
// speedup vs baseline: 1.8048x; 1.3263x over previous
#include <cuda_runtime.h>
#include <cuda_fp16.h>
#include <math.h>
#include <stdint.h>
typedef __half h16;

#define DD    2560
#define HDIM  320
#define NH    8
#define SEGL  1024
#define STOT  4096
#define BATCH 2
#define MMEM  128
#define NSEG  4
#define MBIG  (BATCH*SEGL)
#define MSM   (BATCH*MMEM)
#define BKT   32

// fp32 scratch
__device__ float g_qr[MBIG*DD], g_gate[MBIG*DD], g_kw[MBIG*DD], g_vw[MBIG*DD];
__device__ float g_kr[MSM*DD], g_vr[MSM*DD], g_qw[MSM*DD], g_nm[MSM*DD];
__device__ float g_memA[MSM*DD], g_memB[MSM*DD];
// fp16 scratch
#define WMAT (DD*DD)
__device__ __align__(16) h16 g_whi[11LL*WMAT];
__device__ __align__(16) h16 g_hidhi[BATCH*STOT*DD];
__device__ __align__(16) h16 g_chi[MBIG*DD];
__device__ __align__(16) h16 g_ahi[MBIG*DD];
__device__ __align__(16) h16 g_awhi[MSM*DD];
__device__ __align__(16) h16 g_cathi[MSM*2*DD];
__device__ __align__(16) h16 g_mAhi[MSM*DD];
__device__ __align__(16) h16 g_mBhi[MSM*DD];
__device__ __align__(16) h16 g_imhi[MMEM*DD];
__device__ __align__(16) h16 g_wqhi[MMEM*DD];

#define OW_QR (0LL*WMAT)
#define OW_KR (1LL*WMAT)
#define OW_VR (2LL*WMAT)
#define OW_OR (3LL*WMAT)
#define OW_GR (4LL*WMAT)
#define OW_QW (5LL*WMAT)
#define OW_KW (6LL*WMAT)
#define OW_VW (7LL*WMAT)
#define OW_OW (8LL*WMAT)
#define OW_GW (9LL*WMAT)

__device__ __forceinline__ void cp16(uint32_t s, const void* g) {
    asm volatile("cp.async.cg.shared.global [%0], [%1], 16;\n" :: "r"(s), "l"(g));
}
__device__ __forceinline__ void ldsm4(uint32_t& r0, uint32_t& r1, uint32_t& r2,
                                      uint32_t& r3, uint32_t a) {
    asm volatile("ldmatrix.sync.aligned.m8n8.x4.shared.b16 {%0,%1,%2,%3}, [%4];"
                 : "=r"(r0), "=r"(r1), "=r"(r2), "=r"(r3) : "r"(a));
}
__device__ __forceinline__ void ldsm4t(uint32_t& r0, uint32_t& r1, uint32_t& r2,
                                       uint32_t& r3, uint32_t a) {
    asm volatile("ldmatrix.sync.aligned.m8n8.x4.trans.shared.b16 {%0,%1,%2,%3}, [%4];"
                 : "=r"(r0), "=r"(r1), "=r"(r2), "=r"(r3) : "r"(a));
}
__device__ __forceinline__ void mma16816(float* c, const uint32_t* a, const uint32_t* b) {
    asm volatile("mma.sync.aligned.m16n8k16.row.col.f32.f16.f16.f32 "
                 "{%0,%1,%2,%3}, {%4,%5,%6,%7}, {%8,%9}, {%0,%1,%2,%3};"
                 : "+f"(c[0]), "+f"(c[1]), "+f"(c[2]), "+f"(c[3])
                 : "r"(a[0]), "r"(a[1]), "r"(a[2]), "r"(a[3]), "r"(b[0]), "r"(b[1]));
}
__device__ __forceinline__ float sig_(float x) { return 1.0f / (1.0f + __expf(-x)); }

// ---- single-pass fp16 HMMA GEMM: C = Ah@Wh, fp32 accumulate ----------------
template<int BM, int BN_, int MT, int NT_, int EPI, bool SPLIT>
__global__ void __launch_bounds__(256, 2)
mma_gemm(const h16* __restrict__ Ah, const h16* __restrict__ Wh,
         float* __restrict__ C, h16* __restrict__ Shi,
         int N, int K, int a_cr, long long a_cs, int c_cr, long long c_cs,
         const float* __restrict__ aux0, const float* __restrict__ aux1,
         const float* __restrict__ aux2) {
    constexpr int WM = MT * 16, WN = NT_ * 8;
    constexpr int A_ROWB = BKT * 2 + 16;
    constexpr int B_ROWB = BN_ * 2 + 16;
    constexpr int A_TILE = BM * A_ROWB;
    constexpr int B_TILE = BKT * B_ROWB;
    constexpr int STAGE = A_TILE + B_TILE;
    constexpr int BCH = BN_ / 8;

    extern __shared__ char smem_raw[];
    const uint32_t sbase = (uint32_t)__cvta_generic_to_shared(smem_raw);

    const int tid = threadIdx.x;
    const int m0 = blockIdx.y * BM, n0 = blockIdx.x * BN_;
    const int warp = tid >> 5, lane = tid & 31;
    const int wid_m = warp >> 1, wid_n = warp & 1;
    const long long arow0 = (long long)(m0 / a_cr) * a_cs + (m0 % a_cr);

    float acc[MT][NT_][4];
#pragma unroll
    for (int i = 0; i < MT; ++i)
#pragma unroll
        for (int j = 0; j < NT_; ++j)
#pragma unroll
            for (int e = 0; e < 4; ++e) acc[i][j][e] = 0.0f;

    const int NKI = K / BKT;

    auto ldst = [&](int ks, int st) {
        const int k0 = ks * BKT;
        const uint32_t sb = sbase + st * STAGE;
#pragma unroll
        for (int t = 0; t < (BM * 4) / 256; ++t) {
            const int c = tid + t * 256;
            const int r = c >> 2, kc = (c & 3) * 8;
            const uint32_t off = r * A_ROWB + kc * 2;
            const long long gi = (arow0 + r) * (long long)K + k0 + kc;
            cp16(sb + off, Ah + gi);
        }
        for (int c = tid; c < 4 * BN_; c += 256) {
            const int r = c / BCH, nc = c % BCH;
            const uint32_t off = A_TILE + r * B_ROWB + nc * 16;
            const long long gi = (long long)(k0 + r) * N + n0 + nc * 8;
            cp16(sb + off, Wh + gi);
        }
        asm volatile("cp.async.commit_group;\n");
    };

    ldst(0, 0);
    ldst(1, 1);

    for (int ks = 0; ks < NKI; ++ks) {
        if (ks < NKI - 1) asm volatile("cp.async.wait_group 1;\n");
        else              asm volatile("cp.async.wait_group 0;\n");
        __syncthreads();
        const uint32_t sb = sbase + (ks & 1) * STAGE;

#pragma unroll
        for (int kk = 0; kk < BKT; kk += 16) {
            uint32_t ah[MT][4], b[NT_][2];
            const int arow = wid_m * WM + (lane & 15);
            const int acol = kk + (lane >> 4) * 8;
#pragma unroll
            for (int i = 0; i < MT; ++i) {
                const uint32_t ad = sb + (arow + i * 16) * A_ROWB + acol * 2;
                ldsm4(ah[i][0], ah[i][1], ah[i][2], ah[i][3], ad);
            }
            const int brow = kk + (lane & 15);
            const uint32_t bbase = sb + A_TILE + brow * B_ROWB;
#pragma unroll
            for (int j2 = 0; j2 < NT_ / 2; ++j2) {
                const int bcol = wid_n * WN + j2 * 16 + (lane >> 4) * 8;
                ldsm4t(b[2*j2][0], b[2*j2][1], b[2*j2+1][0], b[2*j2+1][1],
                       bbase + bcol * 2);
            }
#pragma unroll
            for (int i = 0; i < MT; ++i)
#pragma unroll
                for (int j = 0; j < NT_; ++j)
                    mma16816(acc[i][j], ah[i], b[j]);
        }
        __syncthreads();
        if (ks + 2 < NKI) ldst(ks + 2, ks & 1);
    }

    const int gid = lane >> 2, tig = lane & 3;
    const long long crow0 = (long long)(m0 / c_cr) * c_cs + (m0 % c_cr);

#pragma unroll
    for (int i = 0; i < MT; ++i) {
        const int r = wid_m * WM + i * 16 + gid;
#pragma unroll
        for (int j = 0; j < NT_; ++j) {
            const int col = n0 + wid_n * WN + j * 8 + 2 * tig;
#pragma unroll
            for (int half = 0; half < 2; ++half) {
                const int rr = r + half * 8;
                const long long ci = (crow0 + rr) * (long long)N + col;
                const long long li = (long long)(m0 + rr) * N + col;
                float2 v;
#pragma unroll
                for (int e = 0; e < 2; ++e) {
                    const float a = acc[i][j][2 * half + e];
                    float o;
                    if      (EPI == 0) o = a;
                    else if (EPI == 1) o = sig_(a + aux0[col + e]);
                    else if (EPI == 2) o = aux1[ci + e] + aux2[li + e] * a;
                    else { const float s = sig_(a + aux0[col + e]);
                           o = s * aux1[li + e] + (1.0f - s) * aux2[li + e]; }
                    (&v.x)[e] = o;
                }
                *reinterpret_cast<float2*>(C + ci) = v;
                if (SPLIT) {
                    *reinterpret_cast<__half2*>(Shi + li) =
                        __half2(__float2half_rn(v.x), __float2half_rn(v.y));
                }
            }
        }
    }
}

// ---- flash attention: 16 queries/block, warp w owns queries 2w, 2w+1 -------
__global__ void __launch_bounds__(256)
attn16(const float* __restrict__ Q, const float* __restrict__ Kp,
       const float* __restrict__ V, h16* __restrict__ Ohi,
       int Lq, int Lk, float scale) {
    __shared__ float Ks[16][HDIM], Vs[16][HDIM];
    const int h = blockIdx.y, b = blockIdx.z, q0 = blockIdx.x * 16;
    const int tid = threadIdx.x, w = tid >> 5, l = tid & 31;
    const int qa = q0 + 2 * w;

    float qA[10], qB[10];
    const float* Qb = Q + ((long long)(b * Lq + qa)) * DD + h * HDIM;
#pragma unroll
    for (int t = 0; t < 10; ++t) { qA[t] = Qb[l + 32 * t]; qB[t] = Qb[DD + l + 32 * t]; }

    float mrun = -1e30f, sA = 0.0f, sB = 0.0f, accA[10], accB[10];
#pragma unroll
    for (int t = 0; t < 10; ++t) { accA[t] = 0.0f; accB[t] = 0.0f; }

    for (int c = 0; c < Lk / 16; ++c) {
        const long long k0 = (long long)(b * Lk + c * 16) * DD + h * HDIM;
#pragma unroll
        for (int t = 0; t < 5; ++t) {
            const int idx = tid + t * 256;
            const int row = idx / 80, c4 = idx % 80;
            *reinterpret_cast<float4*>(&Ks[row][c4 * 4]) =
                *reinterpret_cast<const float4*>(Kp + k0 + (long long)row * DD + c4 * 4);
            *reinterpret_cast<float4*>(&Vs[row][c4 * 4]) =
                *reinterpret_cast<const float4*>(V + k0 + (long long)row * DD + c4 * 4);
        }
        __syncthreads();
        float scA[16], scB[16], cmax = -1e30f;
#pragma unroll
        for (int k = 0; k < 16; ++k) {
            float da = 0.0f, db = 0.0f;
#pragma unroll
            for (int t = 0; t < 10; ++t) {
                const float kv = Ks[k][l + 32 * t];
                da += qA[t] * kv; db += qB[t] * kv;
            }
#pragma unroll
            for (int o = 16; o > 0; o >>= 1) {
                da += __shfl_xor_sync(0xFFFFFFFF, da, o);
                db += __shfl_xor_sync(0xFFFFFFFF, db, o);
            }
            scA[k] = da * scale; scB[k] = db * scale;
            cmax = fmaxf(cmax, fmaxf(scA[k], scB[k]));
        }
        const float mn = fmaxf(mrun, cmax);
        const float cr = __expf(mrun - mn);
        sA *= cr; sB *= cr;
#pragma unroll
        for (int t = 0; t < 10; ++t) { accA[t] *= cr; accB[t] *= cr; }
        mrun = mn;
#pragma unroll
        for (int k = 0; k < 16; ++k) {
            const float pa = __expf(scA[k] - mn), pb = __expf(scB[k] - mn);
            sA += pa; sB += pb;
#pragma unroll
            for (int t = 0; t < 10; ++t) {
                const float vv = Vs[k][l + 32 * t];
                accA[t] += pa * vv; accB[t] += pb * vv;
            }
        }
        __syncthreads();
    }
    const float iA = 1.0f / sA, iB = 1.0f / sB;
    h16* Oh = Ohi + ((long long)(b * Lq + qa)) * DD + h * HDIM;
#pragma unroll
    for (int t = 0; t < 10; ++t) {
        Oh[l + 32 * t]      = __float2half_rn(accA[t] * iA);
        Oh[DD + l + 32 * t] = __float2half_rn(accB[t] * iB);
    }
}

struct WSrc { const float* p[11]; };

__global__ void wsplit_all(WSrc ws, h16* __restrict__ hi) {
    const int mat = blockIdx.y;
    const long long o = (long long)mat * WMAT + (long long)blockIdx.x * 256 + threadIdx.x;
    hi[o] = __float2half_rn(ws.p[mat][(long long)blockIdx.x * 256 + threadIdx.x]);
}

__global__ void split_id(const float* __restrict__ x, h16* __restrict__ hi) {
    const long long o = (long long)blockIdx.x * 256 + threadIdx.x;
    hi[o] = __float2half_rn(x[o]);
}

__global__ void concat_split(const float* __restrict__ mem, const float* __restrict__ nm,
                             h16* __restrict__ hi) {
    const long long idx = (long long)blockIdx.x * 256 + threadIdx.x;
    const long long r = idx / (2 * DD);
    const int c = (int)(idx % (2 * DD));
    const float v = (c < DD) ? mem[r * DD + c] : nm[r * DD + c - DD];
    hi[idx] = __float2half_rn(v);
}

// ---- side streams for fork/join concurrency (created pre-main) -------------
struct SideStreams {
    cudaStream_t s1, s2;
    cudaEvent_t e0, eWs, eQG, eKVr, eOr, eVW, eMem;
    bool ok;
    SideStreams() {
        ok = cudaStreamCreateWithFlags(&s1, cudaStreamNonBlocking) == cudaSuccess &&
             cudaStreamCreateWithFlags(&s2, cudaStreamNonBlocking) == cudaSuccess &&
             cudaEventCreateWithFlags(&e0,  cudaEventDisableTiming) == cudaSuccess &&
             cudaEventCreateWithFlags(&eWs, cudaEventDisableTiming) == cudaSuccess &&
             cudaEventCreateWithFlags(&eQG, cudaEventDisableTiming) == cudaSuccess &&
             cudaEventCreateWithFlags(&eKVr,cudaEventDisableTiming) == cudaSuccess &&
             cudaEventCreateWithFlags(&eOr, cudaEventDisableTiming) == cudaSuccess &&
             cudaEventCreateWithFlags(&eVW, cudaEventDisableTiming) == cudaSuccess &&
             cudaEventCreateWithFlags(&eMem,cudaEventDisableTiming) == cudaSuccess;
    }
};
static SideStreams SS;

extern "C" void kernel_launch(void* const* d_in, const int* in_sizes, int n_in,
                              void* d_out, int out_size) {
    const float* hid      = (const float*)d_in[0];
    const float* init_mem = (const float*)d_in[1];
    const float* wq_r = (const float*)d_in[2];
    const float* wk_r = (const float*)d_in[3];
    const float* wv_r = (const float*)d_in[4];
    const float* wo_r = (const float*)d_in[5];
    const float* wg_r = (const float*)d_in[6];
    const float* bg_r = (const float*)d_in[7];
    const float* wqueries = (const float*)d_in[8];
    const float* wq_w = (const float*)d_in[9];
    const float* wk_w = (const float*)d_in[10];
    const float* wv_w = (const float*)d_in[11];
    const float* wo_w = (const float*)d_in[12];
    const float* wg_w = (const float*)d_in[13];
    const float* bg_w = (const float*)d_in[14];
    float* out = (float*)d_out;

    float *qr, *gate, *kw, *vw, *kr, *vr, *qw, *nm, *memA, *memB;
    h16 *whi, *hidhi, *chi, *ahi, *awhi, *cathi, *mAhi, *mBhi, *imhi, *wqhi;
    cudaGetSymbolAddress((void**)&qr, g_qr);     cudaGetSymbolAddress((void**)&gate, g_gate);
    cudaGetSymbolAddress((void**)&kw, g_kw);     cudaGetSymbolAddress((void**)&vw, g_vw);
    cudaGetSymbolAddress((void**)&kr, g_kr);     cudaGetSymbolAddress((void**)&vr, g_vr);
    cudaGetSymbolAddress((void**)&qw, g_qw);     cudaGetSymbolAddress((void**)&nm, g_nm);
    cudaGetSymbolAddress((void**)&memA, g_memA); cudaGetSymbolAddress((void**)&memB, g_memB);
    cudaGetSymbolAddress((void**)&whi, g_whi);
    cudaGetSymbolAddress((void**)&hidhi, g_hidhi);
    cudaGetSymbolAddress((void**)&chi, g_chi);
    cudaGetSymbolAddress((void**)&ahi, g_ahi);
    cudaGetSymbolAddress((void**)&awhi, g_awhi);
    cudaGetSymbolAddress((void**)&cathi, g_cathi);
    cudaGetSymbolAddress((void**)&mAhi, g_mAhi);
    cudaGetSymbolAddress((void**)&mBhi, g_mBhi);
    cudaGetSymbolAddress((void**)&imhi, g_imhi);
    cudaGetSymbolAddress((void**)&wqhi, g_wqhi);

    constexpr int SMEM_BIG = 2 * (128 * 80 + 32 * 336);   // 41984
    constexpr int SMEM_SM  = 2 * (64  * 80 + 32 * 144);   // 19456
    cudaFuncSetAttribute(mma_gemm<128,160,2,10,0,false>, cudaFuncAttributeMaxDynamicSharedMemorySize, SMEM_BIG);
    cudaFuncSetAttribute(mma_gemm<128,160,2,10,1,false>, cudaFuncAttributeMaxDynamicSharedMemorySize, SMEM_BIG);
    cudaFuncSetAttribute(mma_gemm<128,160,2,10,2,true >, cudaFuncAttributeMaxDynamicSharedMemorySize, SMEM_BIG);
    cudaFuncSetAttribute(mma_gemm<64,64,1,4,0,false>,    cudaFuncAttributeMaxDynamicSharedMemorySize, SMEM_SM);
    cudaFuncSetAttribute(mma_gemm<64,64,1,4,0,true >,    cudaFuncAttributeMaxDynamicSharedMemorySize, SMEM_SM);
    cudaFuncSetAttribute(mma_gemm<64,64,1,4,3,true >,    cudaFuncAttributeMaxDynamicSharedMemorySize, SMEM_SM);

    const float scale = 0.05590169943749474f;
    const size_t memBytesF = (size_t)MMEM * DD * sizeof(float);
    dim3 gBig(DD / 160, MBIG / 128);   // 256 blocks
    dim3 gSm (DD / 64,  MSM / 64);     // 160 blocks
    dim3 gQw (DD / 64,  MMEM / 64);    // 80 blocks

    const bool ok = SS.ok;
    cudaStream_t t1 = ok ? SS.s1 : 0;
    cudaStream_t t2 = ok ? SS.s2 : 0;

    // ---- prologue ----
    if (ok) { cudaEventRecord(SS.e0, 0); cudaStreamWaitEvent(t1, SS.e0, 0);
              cudaStreamWaitEvent(t2, SS.e0, 0); }
    WSrc ws;
    ws.p[0] = wq_r; ws.p[1] = wk_r; ws.p[2] = wv_r; ws.p[3] = wo_r; ws.p[4] = wg_r;
    ws.p[5] = wq_w; ws.p[6] = wk_w; ws.p[7] = wv_w; ws.p[8] = wo_w;
    ws.p[9] = wg_w; ws.p[10] = wg_w + (long long)WMAT;
    wsplit_all<<<dim3(WMAT/256, 11), 256, 0, 0>>>(ws, whi);
    if (ok) cudaEventRecord(SS.eWs, 0);

    split_id<<<(BATCH*STOT*DD)/256, 256, 0, t1>>>(hid, hidhi);
    split_id<<<(MMEM*DD)/256, 256, 0, t2>>>(init_mem, imhi);
    split_id<<<(MMEM*DD)/256, 256, 0, t2>>>(wqueries, wqhi);

    if (ok) { cudaStreamWaitEvent(t1, SS.eWs, 0); cudaStreamWaitEvent(t2, SS.eWs, 0); }
    // t2: qw chain + kr/vr(0)
    mma_gemm<64,64,1,4,0,false><<<gQw, 256, SMEM_SM, t2>>>(wqhi,
        whi+OW_QW, qw, nullptr, DD, DD, MMEM, 0, MMEM, 0,
        nullptr, nullptr, nullptr);
    cudaMemcpyAsync(qw + (size_t)MMEM*DD, qw, memBytesF, cudaMemcpyDeviceToDevice, t2);
    mma_gemm<64,64,1,4,0,false><<<gSm, 256, SMEM_SM, t2>>>(imhi,
        whi+OW_KR, kr, nullptr, DD, DD, MMEM, 0, MSM, 0,
        nullptr, nullptr, nullptr);
    mma_gemm<64,64,1,4,0,false><<<gSm, 256, SMEM_SM, t2>>>(imhi,
        whi+OW_VR, vr, nullptr, DD, DD, MMEM, 0, MSM, 0,
        nullptr, nullptr, nullptr);
    if (ok) cudaEventRecord(SS.eKVr, t2);
    // t1: qr(0)/gate(0)
    mma_gemm<128,160,2,10,0,false><<<gBig, 256, SMEM_BIG, t1>>>(hidhi,
        whi+OW_QR, qr, nullptr, DD, DD,
        SEGL, (long long)STOT, MBIG, 0, nullptr, nullptr, nullptr);
    mma_gemm<128,160,2,10,1,false><<<gBig, 256, SMEM_BIG, t1>>>(hidhi,
        whi+OW_GR, gate, nullptr, DD, DD,
        SEGL, (long long)STOT, MBIG, 0, bg_r, nullptr, nullptr);
    if (ok) cudaEventRecord(SS.eQG, t1);

    float* memf[2] = {memA, memB};
    h16*   memh[2] = {mAhi, mBhi};
    int cur = 0;

    for (int i = 0; i < NSEG; ++i) {
        const float* segp = hid + (long long)i * SEGL * DD;
        float* outp = out + (long long)i * SEGL * DD;
        const h16* nshi = hidhi + (long long)(i+1) * SEGL * DD;
        const bool NS = (i + 1 < NSEG);

        if (ok) { cudaStreamWaitEvent(0, SS.eQG, 0); cudaStreamWaitEvent(0, SS.eKVr, 0); }
        attn16<<<dim3(SEGL/16, NH, BATCH), 256, 0, 0>>>(qr, kr, vr, chi,
                                                        SEGL, MMEM, scale);
        mma_gemm<128,160,2,10,2,true><<<gBig, 256, SMEM_BIG, 0>>>(chi,
            whi+OW_OR, outp, ahi, DD, DD,
            MBIG, 0, SEGL, (long long)STOT, nullptr, segp, gate);
        if (ok) cudaEventRecord(SS.eOr, 0);

        if (NS) {
            if (ok) cudaStreamWaitEvent(t2, SS.eOr, 0);
            mma_gemm<128,160,2,10,0,false><<<gBig, 256, SMEM_BIG, t2>>>(nshi,
                whi+OW_QR, qr, nullptr, DD, DD,
                SEGL, (long long)STOT, MBIG, 0, nullptr, nullptr, nullptr);
            mma_gemm<128,160,2,10,1,false><<<gBig, 256, SMEM_BIG, t2>>>(nshi,
                whi+OW_GR, gate, nullptr, DD, DD,
                SEGL, (long long)STOT, MBIG, 0, bg_r, nullptr, nullptr);
            if (ok) cudaEventRecord(SS.eQG, t2);
        }

        mma_gemm<128,160,2,10,0,false><<<gBig, 256, SMEM_BIG, 0>>>(ahi,
            whi+OW_KW, kw, nullptr, DD, DD,
            MBIG, 0, MBIG, 0, nullptr, nullptr, nullptr);
        if (ok) cudaStreamWaitEvent(t1, SS.eOr, 0);
        mma_gemm<128,160,2,10,0,false><<<gBig, 256, SMEM_BIG, t1>>>(ahi,
            whi+OW_VW, vw, nullptr, DD, DD,
            MBIG, 0, MBIG, 0, nullptr, nullptr, nullptr);
        if (ok) { cudaEventRecord(SS.eVW, t1); cudaStreamWaitEvent(0, SS.eVW, 0); }

        attn16<<<dim3(MMEM/16, NH, BATCH), 256, 0, 0>>>(qw, kw, vw, awhi,
                                                        MMEM, SEGL, scale);

        if (i == 0) {
            mma_gemm<64,64,1,4,0,true><<<gSm, 256, SMEM_SM, 0>>>(awhi,
                whi+OW_OW, memf[0], mAhi, DD, DD,
                MSM, 0, MSM, 0, nullptr, nullptr, nullptr);
            cur = 0;
        } else {
            mma_gemm<64,64,1,4,0,false><<<gSm, 256, SMEM_SM, 0>>>(awhi,
                whi+OW_OW, nm, nullptr, DD, DD,
                MSM, 0, MSM, 0, nullptr, nullptr, nullptr);
            const int nxt = cur ^ 1;
            concat_split<<<(MSM*2*DD)/256, 256, 0, 0>>>(memf[cur], nm, cathi);
            mma_gemm<64,64,1,4,3,true><<<gSm, 256, SMEM_SM, 0>>>(cathi,
                whi+OW_GW, memf[nxt], memh[nxt], DD, 2*DD,
                MSM, 0, MSM, 0, bg_w, nm, memf[cur]);
            cur = nxt;
        }
        if (ok) cudaEventRecord(SS.eMem, 0);

        if (NS) {
            if (ok) cudaStreamWaitEvent(t1, SS.eMem, 0);
            mma_gemm<64,64,1,4,0,false><<<gSm, 256, SMEM_SM, t1>>>(memh[cur],
                whi+OW_KR, kr, nullptr, DD, DD,
                MSM, 0, MSM, 0, nullptr, nullptr, nullptr);
            mma_gemm<64,64,1,4,0,false><<<gSm, 256, SMEM_SM, t1>>>(memh[cur],
                whi+OW_VR, vr, nullptr, DD, DD,
                MSM, 0, MSM, 0, nullptr, nullptr, nullptr);
            if (ok) cudaEventRecord(SS.eKVr, t1);
        }
    }
}